// round 13
// baseline (speedup 1.0000x reference)
#include <cuda_runtime.h>
#include <cuda_fp16.h>
#include <math_constants.h>
#include <cstdint>
#include <cstddef>

#define S_LEN  2048
#define DIMM   2048
#define NHEADS 16
#define HD     128
#define QKV_W  6144
#define BATCH  2
#define MROWS  (BATCH * S_LEN)   // 4096
#define SCALE_F 0.08838834764831845f

// ---------------------------------------------------------------------------
// Scratch (__device__ globals: allocation-free rule)
// ---------------------------------------------------------------------------
__device__ __half  g_xh[(size_t)MROWS * DIMM];
__device__ __half  g_xl[(size_t)MROWS * DIMM];
__device__ __half  g_wqT_h[(size_t)QKV_W * DIMM];   // [6144,2048] K-major (B^T), hi only
__device__ __half  g_woT_h[(size_t)DIMM * DIMM];    // [2048,2048] K-major, hi only
__device__ __half  g_ah[(size_t)MROWS * DIMM];      // attention out (fp16)
// per-(b,h) attention operands [b][h][s][128]
#define HSD ((size_t)BATCH * NHEADS * S_LEN * HD)
__device__ __half  g_qh[HSD];
__device__ __half  g_ql[HSD];
__device__ __half  g_kh[HSD];   // hi only
__device__ __half  g_vh[HSD];   // hi only

// ---------------------------------------------------------------------------
// helpers
// ---------------------------------------------------------------------------
__device__ __forceinline__ uint32_t smem_u32(const void* p) {
    uint32_t a;
    asm("{ .reg .u64 t; cvta.to.shared.u64 t, %1; cvt.u32.u64 %0, t; }"
        : "=r"(a) : "l"(p));
    return a;
}
__device__ __forceinline__ void cp16(uint32_t dst, const void* src) {
    asm volatile("cp.async.cg.shared.global [%0], [%1], 16;"
                 :: "r"(dst), "l"(src) : "memory");
}
__device__ __forceinline__ void cp_commit() {
    asm volatile("cp.async.commit_group;" ::: "memory");
}
__device__ __forceinline__ void cp_wait1() {
    asm volatile("cp.async.wait_group 1;" ::: "memory");
}
__device__ __forceinline__ void cp_wait2() {
    asm volatile("cp.async.wait_group 2;" ::: "memory");
}
__device__ __forceinline__ void mma_f16(float* d, const uint32_t* a,
                                        const uint32_t* b) {
    asm volatile(
        "mma.sync.aligned.m16n8k16.row.col.f32.f16.f16.f32 "
        "{%0,%1,%2,%3}, {%4,%5,%6,%7}, {%8,%9}, {%0,%1,%2,%3};"
        : "+f"(d[0]), "+f"(d[1]), "+f"(d[2]), "+f"(d[3])
        : "r"(a[0]), "r"(a[1]), "r"(a[2]), "r"(a[3]), "r"(b[0]), "r"(b[1]));
}
__device__ __forceinline__ void ldsm4(uint32_t* r, uint32_t addr) {
    asm volatile("ldmatrix.sync.aligned.m8n8.x4.shared.b16 {%0,%1,%2,%3}, [%4];"
                 : "=r"(r[0]), "=r"(r[1]), "=r"(r[2]), "=r"(r[3]) : "r"(addr));
}
__device__ __forceinline__ void ldsm4t(uint32_t* r, uint32_t addr) {
    asm volatile("ldmatrix.sync.aligned.m8n8.x4.trans.shared.b16 {%0,%1,%2,%3}, [%4];"
                 : "=r"(r[0]), "=r"(r[1]), "=r"(r[2]), "=r"(r[3]) : "r"(addr));
}
// pack two floats into fp16x2 hi; residuals into fp16x2 lo
__device__ __forceinline__ uint32_t pack_hl(float x, float y, uint32_t& lo) {
    __half hx = __float2half_rn(x), hy = __float2half_rn(y);
    float rx = x - __half2float(hx), ry = y - __half2float(hy);
    unsigned short lx = __half_as_ushort(__float2half_rn(rx));
    unsigned short ly = __half_as_ushort(__float2half_rn(ry));
    lo = ((uint32_t)ly << 16) | lx;
    return ((uint32_t)__half_as_ushort(hy) << 16) | __half_as_ushort(hx);
}
__device__ __forceinline__ uint32_t pack_h(float x, float y) {
    return ((uint32_t)__half_as_ushort(__float2half_rn(y)) << 16)
         | (uint32_t)__half_as_ushort(__float2half_rn(x));
}

// ---------------------------------------------------------------------------
// Conversion kernels
// ---------------------------------------------------------------------------
__global__ void split_kernel(const float* __restrict__ in,
                             __half* __restrict__ hi,
                             __half* __restrict__ lo, int n4)
{
    int i = blockIdx.x * blockDim.x + threadIdx.x;
    if (i >= n4) return;
    float4 v = ((const float4*)in)[i];
    uint32_t lo0, lo1;
    uint32_t h0 = pack_hl(v.x, v.y, lo0);
    uint32_t h1 = pack_hl(v.z, v.w, lo1);
    ((uint32_t*)hi)[i * 2]     = h0;
    ((uint32_t*)hi)[i * 2 + 1] = h1;
    ((uint32_t*)lo)[i * 2]     = lo0;
    ((uint32_t*)lo)[i * 2 + 1] = lo1;
}

// in [R,C] fp32 -> out [C,R] fp16 (hi only)
__global__ void transpose_half(const float* __restrict__ in,
                               __half* __restrict__ oh, int R, int C)
{
    __shared__ float t[32][33];
    int bx = blockIdx.x * 32, by = blockIdx.y * 32;
    int x = threadIdx.x, y = threadIdx.y;           // 32 x 8
    #pragma unroll
    for (int i = 0; i < 32; i += 8)
        t[y + i][x] = in[(size_t)(by + y + i) * C + bx + x];
    __syncthreads();
    #pragma unroll
    for (int i = 0; i < 32; i += 8) {
        float v = t[x][y + i];
        oh[(size_t)(bx + y + i) * R + by + x] = __float2half_rn(v);
    }
}

// ---------------------------------------------------------------------------
// Q-GEMM: mma.sync fp16 2-term, BK=32 (R11 structure).
// 128x128 CTA tile, 256 thr, 8 warps 4x2 (warp tile 32x64), 4-stage pipeline,
// single sync/chunk, 2 CTAs/SM. Epilogue: Q hi/lo (scaled) per-(b,h).
// ---------------------------------------------------------------------------
#define ROWB 64
#define TILE_B (128 * ROWB)        // 8192
#define NSTAGE 4
#define QGEMM_SMEM (NSTAGE * 3 * TILE_B)   // 98304

__device__ __forceinline__ uint32_t swoff(int row, int c16) {
    return (uint32_t)(row * ROWB + (((c16 + (row >> 1)) & 3) << 4));
}

__global__ __launch_bounds__(256, 2) void qgemm_mma(
    const __half* __restrict__ Ah, const __half* __restrict__ Al,
    const __half* __restrict__ Bh,
    __half* __restrict__ QH, __half* __restrict__ QL,
    int M, int N, int K)
{
    extern __shared__ char smem[];
    const uint32_t smem_base = smem_u32(smem);
    const int tid  = threadIdx.x;
    const int wid  = tid >> 5;
    const int lane = tid & 31;
    const int wm   = wid & 3;
    const int wn   = wid >> 2;
    const int bm = blockIdx.y * 128;
    const int bn = blockIdx.x * 128;

    const int lr = tid >> 1;
    const int lcb = (tid & 1) * 2;
    const int r0 = lane >> 2;
    const int c0 = (lane & 3) * 2;

    const int a_row_l = lane & 15;
    const int a_cx    = lane >> 4;
    const int b_row_l = (lane & 7) + ((lane >> 4) << 3);
    const int b_cx    = (lane >> 3) & 1;

    float acc[2][8][4];
    #pragma unroll
    for (int mt = 0; mt < 2; mt++)
        #pragma unroll
        for (int nt = 0; nt < 8; nt++)
            #pragma unroll
            for (int j = 0; j < 4; j++) acc[mt][nt][j] = 0.0f;

    const int NC = K / 32;

    auto issue_tile = [&](const __half* src, int row0, int k0,
                          uint32_t dstbase) {
        const char* g = (const char*)(src + (size_t)(row0 + lr) * K + k0);
        cp16(dstbase + swoff(lr, lcb),     g + lcb * 16);
        cp16(dstbase + swoff(lr, lcb + 1), g + lcb * 16 + 16);
    };
    auto issue_stage = [&](int c) {
        uint32_t base = smem_base + (c % NSTAGE) * (3 * TILE_B);
        int k0 = c * 32;
        issue_tile(Ah, bm, k0, base);
        issue_tile(Al, bm, k0, base + TILE_B);
        issue_tile(Bh, bn, k0, base + 2 * TILE_B);
    };

    issue_stage(0); cp_commit();
    issue_stage(1); cp_commit();
    issue_stage(2); cp_commit();

    for (int c = 0; c < NC; c++) {
        cp_wait2();
        __syncthreads();
        if (c + 3 < NC) issue_stage(c + 3);
        cp_commit();

        const uint32_t sb  = smem_base + (c % NSTAGE) * (3 * TILE_B);
        const uint32_t sAh = sb;
        const uint32_t sAl = sb + TILE_B;
        const uint32_t sBh = sb + 2 * TILE_B;

        #pragma unroll
        for (int kss = 0; kss < 2; kss++) {
            const int ks = kss ^ (wid & 1);
            uint32_t ah[2][4], bx[8][2];

            #pragma unroll
            for (int np = 0; np < 4; np++) {
                int row = wn * 64 + np * 16 + b_row_l;
                uint32_t th[4];
                ldsm4(th, sBh + swoff(row, ks * 2 + b_cx));
                bx[np * 2][0] = th[0]; bx[np * 2][1] = th[1];
                bx[np * 2 + 1][0] = th[2]; bx[np * 2 + 1][1] = th[3];
            }
            #pragma unroll
            for (int mt = 0; mt < 2; mt++) {
                int row = wm * 32 + mt * 16 + a_row_l;
                ldsm4(ah[mt], sAh + swoff(row, ks * 2 + a_cx));
            }
            #pragma unroll
            for (int mt = 0; mt < 2; mt++)
                #pragma unroll
                for (int nt = 0; nt < 8; nt++)
                    mma_f16(acc[mt][nt], ah[mt], bx[nt]);

            {
                uint32_t al[2][4];
                #pragma unroll
                for (int mt = 0; mt < 2; mt++) {
                    int row = wm * 32 + mt * 16 + a_row_l;
                    ldsm4(al[mt], sAl + swoff(row, ks * 2 + a_cx));
                }
                #pragma unroll
                for (int mt = 0; mt < 2; mt++)
                    #pragma unroll
                    for (int nt = 0; nt < 8; nt++)
                        mma_f16(acc[mt][nt], al[mt], bx[nt]);
            }
        }
    }

    // epilogue: Q hi/lo, scaled
    const int hh = (bn >> 7) & 15;
    #pragma unroll
    for (int mt = 0; mt < 2; mt++) {
        int row = bm + wm * 32 + mt * 16 + r0;
        #pragma unroll
        for (int nt = 0; nt < 8; nt++) {
            int d = (wn * 64 + nt * 8 + c0) & 127;
            #pragma unroll
            for (int half = 0; half < 2; half++) {
                int rr = row + half * 8;
                int bb = rr >> 11, ss = rr & 2047;
                size_t dst = (((size_t)(bb * NHEADS + hh)) * S_LEN + ss) * HD + d;
                uint32_t lo, hi;
                hi = pack_hl(acc[mt][nt][half * 2] * SCALE_F,
                             acc[mt][nt][half * 2 + 1] * SCALE_F, lo);
                *(uint32_t*)(QH + dst) = hi;
                *(uint32_t*)(QL + dst) = lo;
            }
        }
    }
}

// ---------------------------------------------------------------------------
// 1-term GEMM, BK=64: D = Ah @ Bh^T. 128x128 CTA tile, 256 thr, warp 32x64.
// 128B swizzled rows (c16 ^ (r&7)); 3-stage 32KB pipeline = 96KB -> 2 CTA/SM.
// Half the barriers of BK=32. SPLIT_OUT routes to K(hi)/V(hi); else fp32 C.
// ---------------------------------------------------------------------------
#define ROWB64 128
#define TILE64_B (128 * ROWB64)      // 16384
#define G1_STAGE (2 * TILE64_B)      // 32768: Ah, Bh
#define G1_SMEM (3 * G1_STAGE)       // 98304

__device__ __forceinline__ uint32_t sw64off(int row, int c16) {
    return (uint32_t)(row * ROWB64 + (((c16 ^ (row & 7)) & 7) << 4));
}

template <bool SPLIT_OUT>
__global__ __launch_bounds__(256, 2) void gemm1_bk64(
    const __half* __restrict__ Ah, const __half* __restrict__ Bh,
    float* __restrict__ C,
    __half* __restrict__ KH, __half* __restrict__ VH,
    int nbase, int M, int N, int K)
{
    extern __shared__ char smem[];
    const uint32_t smem_base = smem_u32(smem);
    const int tid  = threadIdx.x;
    const int wid  = tid >> 5;
    const int lane = tid & 31;
    const int wm   = wid & 3;
    const int wn   = wid >> 2;
    const int bm = blockIdx.y * 128;
    const int bn = blockIdx.x * 128;

    const int lr = tid >> 1;            // load row 0..127
    const int lcb = (tid & 1) * 4;      // chunk base 0 or 4
    const int r0 = lane >> 2;
    const int c0 = (lane & 3) * 2;

    const int a_row_l = lane & 15;
    const int a_cx    = lane >> 4;
    const int b_row_l = (lane & 7) + ((lane >> 4) << 3);
    const int b_cx    = (lane >> 3) & 1;

    float acc[2][8][4];
    #pragma unroll
    for (int mt = 0; mt < 2; mt++)
        #pragma unroll
        for (int nt = 0; nt < 8; nt++)
            #pragma unroll
            for (int j = 0; j < 4; j++) acc[mt][nt][j] = 0.0f;

    const int NC = K / 64;    // 32 chunks

    auto issue_tile = [&](const __half* src, int row0, int k0,
                          uint32_t dstbase) {
        const char* g = (const char*)(src + (size_t)(row0 + lr) * K + k0);
        #pragma unroll
        for (int j = 0; j < 4; j++)
            cp16(dstbase + sw64off(lr, lcb + j), g + (lcb + j) * 16);
    };
    auto issue_stage = [&](int c) {
        uint32_t base = smem_base + (c % 3) * G1_STAGE;
        int k0 = c * 64;
        issue_tile(Ah, bm, k0, base);
        issue_tile(Bh, bn, k0, base + TILE64_B);
    };

    issue_stage(0); cp_commit();
    issue_stage(1); cp_commit();

    for (int c = 0; c < NC; c++) {
        cp_wait1();            // stage c ready (c+1 still in flight)
        __syncthreads();
        if (c + 2 < NC) issue_stage(c + 2);
        cp_commit();

        const uint32_t sb  = smem_base + (c % 3) * G1_STAGE;
        const uint32_t sAh = sb;
        const uint32_t sBh = sb + TILE64_B;

        #pragma unroll
        for (int ks = 0; ks < 4; ks++) {
            uint32_t ah[2][4], bx[8][2];
            #pragma unroll
            for (int np = 0; np < 4; np++) {
                int row = wn * 64 + np * 16 + b_row_l;
                uint32_t th[4];
                ldsm4(th, sBh + sw64off(row, ks * 2 + b_cx));
                bx[np * 2][0] = th[0]; bx[np * 2][1] = th[1];
                bx[np * 2 + 1][0] = th[2]; bx[np * 2 + 1][1] = th[3];
            }
            #pragma unroll
            for (int mt = 0; mt < 2; mt++) {
                int row = wm * 32 + mt * 16 + a_row_l;
                ldsm4(ah[mt], sAh + sw64off(row, ks * 2 + a_cx));
            }
            #pragma unroll
            for (int mt = 0; mt < 2; mt++)
                #pragma unroll
                for (int nt = 0; nt < 8; nt++)
                    mma_f16(acc[mt][nt], ah[mt], bx[nt]);
        }
    }

    // epilogue
    if (!SPLIT_OUT) {
        #pragma unroll
        for (int mt = 0; mt < 2; mt++) {
            int row = bm + wm * 32 + mt * 16 + r0;
            #pragma unroll
            for (int nt = 0; nt < 8; nt++) {
                int col = bn + wn * 64 + nt * 8 + c0;
                float* p0 = C + (size_t)row * N + col;
                float* p1 = p0 + 8 * (size_t)N;
                *(float2*)p0 = make_float2(acc[mt][nt][0], acc[mt][nt][1]);
                *(float2*)p1 = make_float2(acc[mt][nt][2], acc[mt][nt][3]);
            }
        }
    } else {
        const int gcol = nbase + bn;
        const int sec = gcol >> 11;         // 1=K, 2=V
        const int hh  = (gcol >> 7) & 15;
        __half* OUT = (sec == 1) ? KH : VH;
        #pragma unroll
        for (int mt = 0; mt < 2; mt++) {
            int row = bm + wm * 32 + mt * 16 + r0;
            #pragma unroll
            for (int nt = 0; nt < 8; nt++) {
                int d = (wn * 64 + nt * 8 + c0) & 127;
                #pragma unroll
                for (int half = 0; half < 2; half++) {
                    int rr = row + half * 8;
                    int bb = rr >> 11, ss = rr & 2047;
                    size_t dst = (((size_t)(bb * NHEADS + hh)) * S_LEN + ss) * HD + d;
                    *(uint32_t*)(OUT + dst) =
                        pack_h(acc[mt][nt][half * 2], acc[mt][nt][half * 2 + 1]);
                }
            }
        }
    }
}

// ---------------------------------------------------------------------------
// Tensor-core flash attention, fp16. QK 2-term; PV 1-term. (R11, unchanged)
// ---------------------------------------------------------------------------
#define BKV 32
#define KV_STAGE_B 16384           // Kh 8KB + Vh 8KB
#define ATT_SMEM (65536 + 3 * KV_STAGE_B)   // 114688

__global__ __launch_bounds__(256, 2) void attn_mma(
    const __half* __restrict__ Qh, const __half* __restrict__ Ql,
    const __half* __restrict__ Kh, const __half* __restrict__ Vh,
    __half* __restrict__ Oh)
{
    extern __shared__ char smem[];
    const uint32_t sb0 = smem_u32(smem);
    const uint32_t sQh = sb0, sQl = sb0 + 32768;
    const int tid = threadIdx.x, wid = tid >> 5, lane = tid & 31;
    const int q0 = blockIdx.x * 128, h = blockIdx.y, b = blockIdx.z;

    const size_t hb = ((size_t)(b * NHEADS + h)) * S_LEN * HD;
    const __half* gqh = Qh + hb + (size_t)q0 * HD;
    const __half* gql = Ql + hb + (size_t)q0 * HD;
    const __half* gkh = Kh + hb;
    const __half* gvh = Vh + hb;

    // Q (128 rows x 256B), hi + lo
    {
        int r = tid >> 1, cb = (tid & 1) * 8;
        const char* g0 = (const char*)(gqh + (size_t)r * HD);
        const char* g1 = (const char*)(gql + (size_t)r * HD);
        uint32_t d0 = sQh + r * 256, d1 = sQl + r * 256;
        #pragma unroll
        for (int j = 0; j < 8; j++) {
            int c = cb + j;
            uint32_t sw = (uint32_t)((c ^ (r & 7)) << 4);
            cp16(d0 + sw, g0 + c * 16);
            cp16(d1 + sw, g1 + c * 16);
        }
    }
    auto ld_stage = [&](int t) {
        uint32_t base = sb0 + 65536 + (t % 3) * KV_STAGE_B;
        int s0 = t * BKV;
        int r = tid >> 3;
        int cb = (tid & 7) * 2;
        const char* gk = (const char*)(gkh + (size_t)(s0 + r) * HD);
        const char* gv = (const char*)(gvh + (size_t)(s0 + r) * HD);
        uint32_t dr = base + r * 256;
        #pragma unroll
        for (int j = 0; j < 2; j++) {
            int c = cb + j;
            uint32_t sw = (uint32_t)((c ^ (r & 7)) << 4);
            cp16(dr + sw,        gk + c * 16);
            cp16(dr + 8192 + sw, gv + c * 16);
        }
    };

    ld_stage(0); cp_commit();      // Q rides in group 0
    ld_stage(1); cp_commit();

    const int aq_row = wid * 16 + (lane & 15);
    const uint32_t aq_base = (uint32_t)(aq_row * 256);
    const int aq_r7 = aq_row & 7;
    const int aq_cx = lane >> 4;
    const int bk_row = (lane & 7) + ((lane >> 4) << 3);
    const int bk_cx = (lane >> 3) & 1;
    const int bv_row = (lane & 7) + (((lane >> 3) & 1) << 3);
    const int bv_cx = lane >> 4;

    float o[16][4];
    #pragma unroll
    for (int nt = 0; nt < 16; nt++) { o[nt][0]=o[nt][1]=o[nt][2]=o[nt][3]=0.f; }
    float mr1 = -CUDART_INF_F, mr2 = -CUDART_INF_F, lr1 = 0.f, lr2 = 0.f;

    const int NT = S_LEN / BKV;    // 64
    for (int t = 0; t < NT; t++) {
        cp_wait1();
        __syncthreads();
        if (t + 2 < NT) ld_stage(t + 2);
        cp_commit();

        uint32_t sK = sb0 + 65536 + (t % 3) * KV_STAGE_B;
        uint32_t sV = sK + 8192;

        // ---- S = Q.K^T (2 terms) ----
        float s[4][4];
        #pragma unroll
        for (int i = 0; i < 4; i++) { s[i][0]=s[i][1]=s[i][2]=s[i][3]=0.f; }

        #pragma unroll
        for (int kt = 0; kt < 8; kt++) {
            uint32_t ah4[4], al4[4];
            {
                int c16 = kt * 2 + aq_cx;
                uint32_t off = aq_base + (uint32_t)(((c16 ^ aq_r7)) << 4);
                ldsm4(ah4, sQh + off);
                ldsm4(al4, sQl + off);
            }
            #pragma unroll
            for (int np = 0; np < 2; np++) {
                int row = np * 16 + bk_row;
                int c16 = kt * 2 + bk_cx;
                uint32_t off = (uint32_t)(row * 256) + (uint32_t)(((c16 ^ (row & 7))) << 4);
                uint32_t bh4[4];
                ldsm4(bh4, sK + off);
                mma_f16(s[2*np],   ah4, bh4);
                mma_f16(s[2*np+1], ah4, bh4 + 2);
                mma_f16(s[2*np],   al4, bh4);
                mma_f16(s[2*np+1], al4, bh4 + 2);
            }
        }

        // ---- online softmax ----
        float m1 = s[0][0], m2 = s[0][2];
        #pragma unroll
        for (int i = 0; i < 4; i++) {
            m1 = fmaxf(m1, fmaxf(s[i][0], s[i][1]));
            m2 = fmaxf(m2, fmaxf(s[i][2], s[i][3]));
        }
        m1 = fmaxf(m1, __shfl_xor_sync(0xffffffffu, m1, 1));
        m1 = fmaxf(m1, __shfl_xor_sync(0xffffffffu, m1, 2));
        m2 = fmaxf(m2, __shfl_xor_sync(0xffffffffu, m2, 1));
        m2 = fmaxf(m2, __shfl_xor_sync(0xffffffffu, m2, 2));
        float mn1 = fmaxf(mr1, m1), mn2 = fmaxf(mr2, m2);
        float a1 = __expf(mr1 - mn1), a2 = __expf(mr2 - mn2);
        mr1 = mn1; mr2 = mn2;
        float l1 = 0.f, l2 = 0.f;
        #pragma unroll
        for (int i = 0; i < 4; i++) {
            s[i][0] = __expf(s[i][0] - mn1); s[i][1] = __expf(s[i][1] - mn1);
            s[i][2] = __expf(s[i][2] - mn2); s[i][3] = __expf(s[i][3] - mn2);
            l1 += s[i][0] + s[i][1];
            l2 += s[i][2] + s[i][3];
        }
        l1 += __shfl_xor_sync(0xffffffffu, l1, 1);
        l1 += __shfl_xor_sync(0xffffffffu, l1, 2);
        l2 += __shfl_xor_sync(0xffffffffu, l2, 1);
        l2 += __shfl_xor_sync(0xffffffffu, l2, 2);
        lr1 = lr1 * a1 + l1;
        lr2 = lr2 * a2 + l2;
        #pragma unroll
        for (int nt = 0; nt < 16; nt++) {
            o[nt][0] *= a1; o[nt][1] *= a1; o[nt][2] *= a2; o[nt][3] *= a2;
        }

        // ---- pack P -> fp16 A-fragments (hi only) ----
        uint32_t ph[2][4];
        #pragma unroll
        for (int k2 = 0; k2 < 2; k2++) {
            ph[k2][0] = pack_h(s[2*k2][0],   s[2*k2][1]);
            ph[k2][1] = pack_h(s[2*k2][2],   s[2*k2][3]);
            ph[k2][2] = pack_h(s[2*k2+1][0], s[2*k2+1][1]);
            ph[k2][3] = pack_h(s[2*k2+1][2], s[2*k2+1][3]);
        }

        // ---- O += P.V (1 term), V via ldmatrix.trans ----
        #pragma unroll
        for (int k2 = 0; k2 < 2; k2++) {
            #pragma unroll
            for (int np = 0; np < 8; np++) {
                int row = k2 * 16 + bv_row;
                int c16 = np * 2 + bv_cx;
                uint32_t off = (uint32_t)(row * 256) + (uint32_t)(((c16 ^ (row & 7))) << 4);
                uint32_t v4[4];
                ldsm4t(v4, sV + off);
                mma_f16(o[2*np],   ph[k2], v4);
                mma_f16(o[2*np+1], ph[k2], v4 + 2);
            }
        }
    }

    // epilogue: normalize, write fp16
    float i1 = 1.f / lr1, i2 = 1.f / lr2;
    int r1 = lane >> 2, c2 = (lane & 3) * 2;
    size_t row1 = (size_t)b * S_LEN + q0 + wid * 16 + r1;
    size_t row2 = row1 + 8;
    #pragma unroll
    for (int nt = 0; nt < 16; nt++) {
        int col = h * HD + nt * 8 + c2;
        *(uint32_t*)(Oh + row1 * DIMM + col) = pack_h(o[nt][0] * i1, o[nt][1] * i1);
        *(uint32_t*)(Oh + row2 * DIMM + col) = pack_h(o[nt][2] * i2, o[nt][3] * i2);
    }
}

// ---------------------------------------------------------------------------
extern "C" void kernel_launch(void* const* d_in, const int* in_sizes, int n_in,
                              void* d_out, int out_size)
{
    const float* x     = (const float*)d_in[0];   // [2,2048,2048]
    const float* w_qkv = (const float*)d_in[1];   // [2048,6144]
    const float* w_out = (const float*)d_in[2];   // [2048,2048]
    float* out = (float*)d_out;                   // [2,2048,2048]

    __half *xh, *xl, *wqh, *woh, *ah, *qh, *ql, *kh, *vh;
    cudaGetSymbolAddress((void**)&xh, g_xh);
    cudaGetSymbolAddress((void**)&xl, g_xl);
    cudaGetSymbolAddress((void**)&wqh, g_wqT_h);
    cudaGetSymbolAddress((void**)&woh, g_woT_h);
    cudaGetSymbolAddress((void**)&ah, g_ah);
    cudaGetSymbolAddress((void**)&qh, g_qh);
    cudaGetSymbolAddress((void**)&ql, g_ql);
    cudaGetSymbolAddress((void**)&kh, g_kh);
    cudaGetSymbolAddress((void**)&vh, g_vh);

    cudaFuncSetAttribute(qgemm_mma,
                         cudaFuncAttributeMaxDynamicSharedMemorySize, QGEMM_SMEM);
    cudaFuncSetAttribute(gemm1_bk64<true>,
                         cudaFuncAttributeMaxDynamicSharedMemorySize, G1_SMEM);
    cudaFuncSetAttribute(gemm1_bk64<false>,
                         cudaFuncAttributeMaxDynamicSharedMemorySize, G1_SMEM);
    cudaFuncSetAttribute(attn_mma,
                         cudaFuncAttributeMaxDynamicSharedMemorySize, ATT_SMEM);

    // split x -> fp16 hi/lo
    {
        int n4 = (MROWS * DIMM) / 4;
        split_kernel<<<(n4 + 255) / 256, 256>>>(x, xh, xl, n4);
    }
    // transpose weights -> fp16 hi only
    {
        dim3 tb(32, 8);
        transpose_half<<<dim3(QKV_W / 32, DIMM / 32), tb>>>(w_qkv, wqh, DIMM, QKV_W);
        transpose_half<<<dim3(DIMM / 32, DIMM / 32), tb>>>(w_out, woh, DIMM, DIMM);
    }
    // 1a) Q projection (2-term, BK=32)
    qgemm_mma<<<dim3(2048 / 128, MROWS / 128), 256, QGEMM_SMEM>>>(
        xh, xl, wqh, qh, ql, MROWS, 2048, DIMM);
    // 1b) K/V projection (1-term, BK=64, half the barriers)
    gemm1_bk64<true><<<dim3(4096 / 128, MROWS / 128), 256, G1_SMEM>>>(
        xh, wqh + (size_t)2048 * DIMM, nullptr, kh, vh,
        2048, MROWS, 4096, DIMM);

    // 2) Attention -> writes fp16 O
    {
        dim3 grid(S_LEN / 128, NHEADS, BATCH);
        attn_mma<<<grid, 256, ATT_SMEM>>>(qh, ql, kh, vh, ah);
    }

    // 3) Output projection -> fp32 out (1-term, BK=64)
    gemm1_bk64<false><<<dim3(DIMM / 128, MROWS / 128), 256, G1_SMEM>>>(
        ah, woh, out, nullptr, nullptr, 0, MROWS, DIMM, DIMM);
}

// round 14
// speedup vs baseline: 1.0358x; 1.0358x over previous
#include <cuda_runtime.h>
#include <cuda_fp16.h>
#include <math_constants.h>
#include <cstdint>
#include <cstddef>

#define S_LEN  2048
#define DIMM   2048
#define NHEADS 16
#define HD     128
#define QKV_W  6144
#define BATCH  2
#define MROWS  (BATCH * S_LEN)   // 4096
#define SCALE_F 0.08838834764831845f

// ---------------------------------------------------------------------------
// Scratch (__device__ globals: allocation-free rule)
// ---------------------------------------------------------------------------
__device__ __half  g_xh[(size_t)MROWS * DIMM];
__device__ __half  g_xl[(size_t)MROWS * DIMM];
__device__ __half  g_wqT_h[(size_t)QKV_W * DIMM];   // [6144,2048] K-major (B^T), hi only
__device__ __half  g_woT_h[(size_t)DIMM * DIMM];    // [2048,2048] K-major, hi only
__device__ __half  g_ah[(size_t)MROWS * DIMM];      // attention out (fp16)
// per-(b,h) attention operands [b][h][s][128]
#define HSD ((size_t)BATCH * NHEADS * S_LEN * HD)
__device__ __half  g_qh[HSD];
__device__ __half  g_ql[HSD];
__device__ __half  g_kh[HSD];   // hi only
__device__ __half  g_vh[HSD];   // hi only

// ---------------------------------------------------------------------------
// helpers
// ---------------------------------------------------------------------------
__device__ __forceinline__ uint32_t smem_u32(const void* p) {
    uint32_t a;
    asm("{ .reg .u64 t; cvta.to.shared.u64 t, %1; cvt.u32.u64 %0, t; }"
        : "=r"(a) : "l"(p));
    return a;
}
__device__ __forceinline__ void cp16(uint32_t dst, const void* src) {
    asm volatile("cp.async.cg.shared.global [%0], [%1], 16;"
                 :: "r"(dst), "l"(src) : "memory");
}
__device__ __forceinline__ void cp_commit() {
    asm volatile("cp.async.commit_group;" ::: "memory");
}
__device__ __forceinline__ void cp_wait1() {
    asm volatile("cp.async.wait_group 1;" ::: "memory");
}
template <int N>
__device__ __forceinline__ void cp_waitn() {
    asm volatile("cp.async.wait_group %0;" :: "n"(N) : "memory");
}
__device__ __forceinline__ void mma_f16(float* d, const uint32_t* a,
                                        const uint32_t* b) {
    asm volatile(
        "mma.sync.aligned.m16n8k16.row.col.f32.f16.f16.f32 "
        "{%0,%1,%2,%3}, {%4,%5,%6,%7}, {%8,%9}, {%0,%1,%2,%3};"
        : "+f"(d[0]), "+f"(d[1]), "+f"(d[2]), "+f"(d[3])
        : "r"(a[0]), "r"(a[1]), "r"(a[2]), "r"(a[3]), "r"(b[0]), "r"(b[1]));
}
__device__ __forceinline__ void ldsm4(uint32_t* r, uint32_t addr) {
    asm volatile("ldmatrix.sync.aligned.m8n8.x4.shared.b16 {%0,%1,%2,%3}, [%4];"
                 : "=r"(r[0]), "=r"(r[1]), "=r"(r[2]), "=r"(r[3]) : "r"(addr));
}
__device__ __forceinline__ void ldsm4t(uint32_t* r, uint32_t addr) {
    asm volatile("ldmatrix.sync.aligned.m8n8.x4.trans.shared.b16 {%0,%1,%2,%3}, [%4];"
                 : "=r"(r[0]), "=r"(r[1]), "=r"(r[2]), "=r"(r[3]) : "r"(addr));
}
// pack two floats into fp16x2 hi; residuals into fp16x2 lo
__device__ __forceinline__ uint32_t pack_hl(float x, float y, uint32_t& lo) {
    __half hx = __float2half_rn(x), hy = __float2half_rn(y);
    float rx = x - __half2float(hx), ry = y - __half2float(hy);
    unsigned short lx = __half_as_ushort(__float2half_rn(rx));
    unsigned short ly = __half_as_ushort(__float2half_rn(ry));
    lo = ((uint32_t)ly << 16) | lx;
    return ((uint32_t)__half_as_ushort(hy) << 16) | __half_as_ushort(hx);
}
__device__ __forceinline__ uint32_t pack_h(float x, float y) {
    return ((uint32_t)__half_as_ushort(__float2half_rn(y)) << 16)
         | (uint32_t)__half_as_ushort(__float2half_rn(x));
}

// ---------------------------------------------------------------------------
// Conversion kernels
// ---------------------------------------------------------------------------
__global__ void split_kernel(const float* __restrict__ in,
                             __half* __restrict__ hi,
                             __half* __restrict__ lo, int n4)
{
    int i = blockIdx.x * blockDim.x + threadIdx.x;
    if (i >= n4) return;
    float4 v = ((const float4*)in)[i];
    uint32_t lo0, lo1;
    uint32_t h0 = pack_hl(v.x, v.y, lo0);
    uint32_t h1 = pack_hl(v.z, v.w, lo1);
    ((uint32_t*)hi)[i * 2]     = h0;
    ((uint32_t*)hi)[i * 2 + 1] = h1;
    ((uint32_t*)lo)[i * 2]     = lo0;
    ((uint32_t*)lo)[i * 2 + 1] = lo1;
}

// in [R,C] fp32 -> out [C,R] fp16 (hi only)
__global__ void transpose_half(const float* __restrict__ in,
                               __half* __restrict__ oh, int R, int C)
{
    __shared__ float t[32][33];
    int bx = blockIdx.x * 32, by = blockIdx.y * 32;
    int x = threadIdx.x, y = threadIdx.y;           // 32 x 8
    #pragma unroll
    for (int i = 0; i < 32; i += 8)
        t[y + i][x] = in[(size_t)(by + y + i) * C + bx + x];
    __syncthreads();
    #pragma unroll
    for (int i = 0; i < 32; i += 8) {
        float v = t[x][y + i];
        oh[(size_t)(bx + y + i) * R + by + x] = __float2half_rn(v);
    }
}

// ---------------------------------------------------------------------------
// mma.sync fp16 GEMM: C = A @ B^T.
// TERMS=2: D ~= Ah*Bh + Al*Bh.   TERMS=1: D ~= Ah*Bh.
// 128x128 CTA tile, BK=32, 256 thr, 8 warps 4x2 (warp tile 32x64).
// STAGES-deep cp.async pipeline, single sync/chunk, 2 CTAs/SM.
// SPLIT_OUT epilogue routes cols (nbase+...) to Q(hi/lo,scaled) / K(hi) / V(hi).
// ---------------------------------------------------------------------------
#define ROWB 64
#define TILE_B (128 * ROWB)        // 8192

__device__ __forceinline__ uint32_t swoff(int row, int c16) {
    return (uint32_t)(row * ROWB + (((c16 + (row >> 1)) & 3) << 4));
}

template <int TERMS, int STAGES, bool SPLIT_OUT>
__global__ __launch_bounds__(256, 2) void gemm_mma(
    const __half* __restrict__ Ah, const __half* __restrict__ Al,
    const __half* __restrict__ Bh,
    float* __restrict__ C,
    __half* __restrict__ QH, __half* __restrict__ QL,
    __half* __restrict__ KH, __half* __restrict__ VH,
    int nbase, int M, int N, int K)
{
    constexpr int STAGEB = (TERMS + 1) * TILE_B;   // Ah [, Al], Bh
    extern __shared__ char smem[];
    const uint32_t smem_base = smem_u32(smem);
    const int tid  = threadIdx.x;
    const int wid  = tid >> 5;
    const int lane = tid & 31;
    const int wm   = wid & 3;          // 0..3  (m dir, 32 rows)
    const int wn   = wid >> 2;         // 0..1  (n dir, 64 cols)
    const int bm = blockIdx.y * 128;
    const int bn = blockIdx.x * 128;

    const int lr = tid >> 1;            // load row 0..127
    const int lcb = (tid & 1) * 2;      // chunk base 0 or 2
    const int r0 = lane >> 2;
    const int c0 = (lane & 3) * 2;

    const int a_row_l = lane & 15;
    const int a_cx    = lane >> 4;
    const int b_row_l = (lane & 7) + ((lane >> 4) << 3);
    const int b_cx    = (lane >> 3) & 1;

    float acc[2][8][4];
    #pragma unroll
    for (int mt = 0; mt < 2; mt++)
        #pragma unroll
        for (int nt = 0; nt < 8; nt++)
            #pragma unroll
            for (int j = 0; j < 4; j++) acc[mt][nt][j] = 0.0f;

    const int NC = K / 32;

    auto issue_tile = [&](const __half* src, int row0, int k0,
                          uint32_t dstbase) {
        const char* g = (const char*)(src + (size_t)(row0 + lr) * K + k0);
        cp16(dstbase + swoff(lr, lcb),     g + lcb * 16);
        cp16(dstbase + swoff(lr, lcb + 1), g + lcb * 16 + 16);
    };
    auto issue_stage = [&](int c) {
        uint32_t base = smem_base + (c % STAGES) * STAGEB;
        int k0 = c * 32;
        issue_tile(Ah, bm, k0, base);
        if constexpr (TERMS == 2) issue_tile(Al, bm, k0, base + TILE_B);
        issue_tile(Bh, bn, k0, base + (TERMS == 2 ? 2 : 1) * TILE_B);
    };

    #pragma unroll
    for (int s = 0; s < STAGES - 1; s++) {
        issue_stage(s);
        cp_commit();
    }

    for (int c = 0; c < NC; c++) {
        cp_waitn<STAGES - 2>();      // stage c complete
        __syncthreads();
        if (c + STAGES - 1 < NC) issue_stage(c + STAGES - 1);
        cp_commit();

        const uint32_t sb  = smem_base + (c % STAGES) * STAGEB;
        const uint32_t sAh = sb;
        const uint32_t sAl = sb + TILE_B;
        const uint32_t sBh = sb + (TERMS == 2 ? 2 : 1) * TILE_B;

        #pragma unroll
        for (int kss = 0; kss < 2; kss++) {
            const int ks = kss ^ (wid & 1);    // warp-staggered phases
            uint32_t ah[2][4], bx[8][2];

            // B fragments (64 n-cols per warp)
            #pragma unroll
            for (int np = 0; np < 4; np++) {
                int row = wn * 64 + np * 16 + b_row_l;
                uint32_t th[4];
                ldsm4(th, sBh + swoff(row, ks * 2 + b_cx));
                bx[np * 2][0] = th[0]; bx[np * 2][1] = th[1];
                bx[np * 2 + 1][0] = th[2]; bx[np * 2 + 1][1] = th[3];
            }
            // pass 1: Ah * Bh
            #pragma unroll
            for (int mt = 0; mt < 2; mt++) {
                int row = wm * 32 + mt * 16 + a_row_l;
                ldsm4(ah[mt], sAh + swoff(row, ks * 2 + a_cx));
            }
            #pragma unroll
            for (int mt = 0; mt < 2; mt++)
                #pragma unroll
                for (int nt = 0; nt < 8; nt++)
                    mma_f16(acc[mt][nt], ah[mt], bx[nt]);

            // pass 2: Al * Bh (reuse bx)
            if constexpr (TERMS == 2) {
                uint32_t al[2][4];
                #pragma unroll
                for (int mt = 0; mt < 2; mt++) {
                    int row = wm * 32 + mt * 16 + a_row_l;
                    ldsm4(al[mt], sAl + swoff(row, ks * 2 + a_cx));
                }
                #pragma unroll
                for (int mt = 0; mt < 2; mt++)
                    #pragma unroll
                    for (int nt = 0; nt < 8; nt++)
                        mma_f16(acc[mt][nt], al[mt], bx[nt]);
            }
        }
    }

    // epilogue
    if (!SPLIT_OUT) {
        #pragma unroll
        for (int mt = 0; mt < 2; mt++) {
            int row = bm + wm * 32 + mt * 16 + r0;
            #pragma unroll
            for (int nt = 0; nt < 8; nt++) {
                int col = bn + wn * 64 + nt * 8 + c0;
                float* p0 = C + (size_t)row * N + col;
                float* p1 = p0 + 8 * (size_t)N;
                *(float2*)p0 = make_float2(acc[mt][nt][0], acc[mt][nt][1]);
                *(float2*)p1 = make_float2(acc[mt][nt][2], acc[mt][nt][3]);
            }
        }
    } else {
        const int gcol = nbase + bn;        // global qkv column of tile start
        const int sec = gcol >> 11;         // 0=Q, 1=K, 2=V
        const int hh  = (gcol >> 7) & 15;
        #pragma unroll
        for (int mt = 0; mt < 2; mt++) {
            int row = bm + wm * 32 + mt * 16 + r0;
            #pragma unroll
            for (int nt = 0; nt < 8; nt++) {
                int d = (wn * 64 + nt * 8 + c0) & 127;
                #pragma unroll
                for (int half = 0; half < 2; half++) {
                    int rr = row + half * 8;
                    int bb = rr >> 11, ss = rr & 2047;
                    size_t dst = (((size_t)(bb * NHEADS + hh)) * S_LEN + ss) * HD + d;
                    float v0 = acc[mt][nt][half * 2];
                    float v1 = acc[mt][nt][half * 2 + 1];
                    if (sec == 0) {
                        uint32_t lo, hi;
                        hi = pack_hl(v0 * SCALE_F, v1 * SCALE_F, lo);
                        *(uint32_t*)(QH + dst) = hi;
                        *(uint32_t*)(QL + dst) = lo;
                    } else if (sec == 1) {
                        *(uint32_t*)(KH + dst) = pack_h(v0, v1);
                    } else {
                        *(uint32_t*)(VH + dst) = pack_h(v0, v1);
                    }
                }
            }
        }
    }
}

// ---------------------------------------------------------------------------
// Tensor-core flash attention, fp16. QK 2-term; PV 1-term. (R11, unchanged)
// ---------------------------------------------------------------------------
#define BKV 32
#define KV_STAGE_B 16384           // Kh 8KB + Vh 8KB
#define ATT_SMEM (65536 + 3 * KV_STAGE_B)   // 114688

__global__ __launch_bounds__(256, 2) void attn_mma(
    const __half* __restrict__ Qh, const __half* __restrict__ Ql,
    const __half* __restrict__ Kh, const __half* __restrict__ Vh,
    __half* __restrict__ Oh)
{
    extern __shared__ char smem[];
    const uint32_t sb0 = smem_u32(smem);
    const uint32_t sQh = sb0, sQl = sb0 + 32768;
    const int tid = threadIdx.x, wid = tid >> 5, lane = tid & 31;
    const int q0 = blockIdx.x * 128, h = blockIdx.y, b = blockIdx.z;

    const size_t hb = ((size_t)(b * NHEADS + h)) * S_LEN * HD;
    const __half* gqh = Qh + hb + (size_t)q0 * HD;
    const __half* gql = Ql + hb + (size_t)q0 * HD;
    const __half* gkh = Kh + hb;
    const __half* gvh = Vh + hb;

    // Q (128 rows x 256B), hi + lo
    {
        int r = tid >> 1, cb = (tid & 1) * 8;
        const char* g0 = (const char*)(gqh + (size_t)r * HD);
        const char* g1 = (const char*)(gql + (size_t)r * HD);
        uint32_t d0 = sQh + r * 256, d1 = sQl + r * 256;
        #pragma unroll
        for (int j = 0; j < 8; j++) {
            int c = cb + j;
            uint32_t sw = (uint32_t)((c ^ (r & 7)) << 4);
            cp16(d0 + sw, g0 + c * 16);
            cp16(d1 + sw, g1 + c * 16);
        }
    }
    auto ld_stage = [&](int t) {
        uint32_t base = sb0 + 65536 + (t % 3) * KV_STAGE_B;
        int s0 = t * BKV;
        int r = tid >> 3;
        int cb = (tid & 7) * 2;
        const char* gk = (const char*)(gkh + (size_t)(s0 + r) * HD);
        const char* gv = (const char*)(gvh + (size_t)(s0 + r) * HD);
        uint32_t dr = base + r * 256;
        #pragma unroll
        for (int j = 0; j < 2; j++) {
            int c = cb + j;
            uint32_t sw = (uint32_t)((c ^ (r & 7)) << 4);
            cp16(dr + sw,        gk + c * 16);
            cp16(dr + 8192 + sw, gv + c * 16);
        }
    };

    ld_stage(0); cp_commit();      // Q rides in group 0
    ld_stage(1); cp_commit();

    const int aq_row = wid * 16 + (lane & 15);
    const uint32_t aq_base = (uint32_t)(aq_row * 256);
    const int aq_r7 = aq_row & 7;
    const int aq_cx = lane >> 4;
    const int bk_row = (lane & 7) + ((lane >> 4) << 3);
    const int bk_cx = (lane >> 3) & 1;
    const int bv_row = (lane & 7) + (((lane >> 3) & 1) << 3);
    const int bv_cx = lane >> 4;

    float o[16][4];
    #pragma unroll
    for (int nt = 0; nt < 16; nt++) { o[nt][0]=o[nt][1]=o[nt][2]=o[nt][3]=0.f; }
    float mr1 = -CUDART_INF_F, mr2 = -CUDART_INF_F, lr1 = 0.f, lr2 = 0.f;

    const int NT = S_LEN / BKV;    // 64
    for (int t = 0; t < NT; t++) {
        cp_wait1();
        __syncthreads();
        if (t + 2 < NT) ld_stage(t + 2);
        cp_commit();

        uint32_t sK = sb0 + 65536 + (t % 3) * KV_STAGE_B;
        uint32_t sV = sK + 8192;

        // ---- S = Q.K^T (2 terms) ----
        float s[4][4];
        #pragma unroll
        for (int i = 0; i < 4; i++) { s[i][0]=s[i][1]=s[i][2]=s[i][3]=0.f; }

        #pragma unroll
        for (int kt = 0; kt < 8; kt++) {
            uint32_t ah4[4], al4[4];
            {
                int c16 = kt * 2 + aq_cx;
                uint32_t off = aq_base + (uint32_t)(((c16 ^ aq_r7)) << 4);
                ldsm4(ah4, sQh + off);
                ldsm4(al4, sQl + off);
            }
            #pragma unroll
            for (int np = 0; np < 2; np++) {
                int row = np * 16 + bk_row;
                int c16 = kt * 2 + bk_cx;
                uint32_t off = (uint32_t)(row * 256) + (uint32_t)(((c16 ^ (row & 7))) << 4);
                uint32_t bh4[4];
                ldsm4(bh4, sK + off);
                mma_f16(s[2*np],   ah4, bh4);
                mma_f16(s[2*np+1], ah4, bh4 + 2);
                mma_f16(s[2*np],   al4, bh4);
                mma_f16(s[2*np+1], al4, bh4 + 2);
            }
        }

        // ---- online softmax (rows r1 = lane>>2 and r1+8) ----
        float m1 = s[0][0], m2 = s[0][2];
        #pragma unroll
        for (int i = 0; i < 4; i++) {
            m1 = fmaxf(m1, fmaxf(s[i][0], s[i][1]));
            m2 = fmaxf(m2, fmaxf(s[i][2], s[i][3]));
        }
        m1 = fmaxf(m1, __shfl_xor_sync(0xffffffffu, m1, 1));
        m1 = fmaxf(m1, __shfl_xor_sync(0xffffffffu, m1, 2));
        m2 = fmaxf(m2, __shfl_xor_sync(0xffffffffu, m2, 1));
        m2 = fmaxf(m2, __shfl_xor_sync(0xffffffffu, m2, 2));
        float mn1 = fmaxf(mr1, m1), mn2 = fmaxf(mr2, m2);
        float a1 = __expf(mr1 - mn1), a2 = __expf(mr2 - mn2);
        mr1 = mn1; mr2 = mn2;
        float l1 = 0.f, l2 = 0.f;
        #pragma unroll
        for (int i = 0; i < 4; i++) {
            s[i][0] = __expf(s[i][0] - mn1); s[i][1] = __expf(s[i][1] - mn1);
            s[i][2] = __expf(s[i][2] - mn2); s[i][3] = __expf(s[i][3] - mn2);
            l1 += s[i][0] + s[i][1];
            l2 += s[i][2] + s[i][3];
        }
        l1 += __shfl_xor_sync(0xffffffffu, l1, 1);
        l1 += __shfl_xor_sync(0xffffffffu, l1, 2);
        l2 += __shfl_xor_sync(0xffffffffu, l2, 1);
        l2 += __shfl_xor_sync(0xffffffffu, l2, 2);
        lr1 = lr1 * a1 + l1;
        lr2 = lr2 * a2 + l2;
        #pragma unroll
        for (int nt = 0; nt < 16; nt++) {
            o[nt][0] *= a1; o[nt][1] *= a1; o[nt][2] *= a2; o[nt][3] *= a2;
        }

        // ---- pack P -> fp16 A-fragments (hi only) ----
        uint32_t ph[2][4];
        #pragma unroll
        for (int k2 = 0; k2 < 2; k2++) {
            ph[k2][0] = pack_h(s[2*k2][0],   s[2*k2][1]);
            ph[k2][1] = pack_h(s[2*k2][2],   s[2*k2][3]);
            ph[k2][2] = pack_h(s[2*k2+1][0], s[2*k2+1][1]);
            ph[k2][3] = pack_h(s[2*k2+1][2], s[2*k2+1][3]);
        }

        // ---- O += P.V (1 term), V via ldmatrix.trans ----
        #pragma unroll
        for (int k2 = 0; k2 < 2; k2++) {
            #pragma unroll
            for (int np = 0; np < 8; np++) {
                int row = k2 * 16 + bv_row;
                int c16 = np * 2 + bv_cx;
                uint32_t off = (uint32_t)(row * 256) + (uint32_t)(((c16 ^ (row & 7))) << 4);
                uint32_t v4[4];
                ldsm4t(v4, sV + off);
                mma_f16(o[2*np],   ph[k2], v4);
                mma_f16(o[2*np+1], ph[k2], v4 + 2);
            }
        }
    }

    // epilogue: normalize, write fp16
    float i1 = 1.f / lr1, i2 = 1.f / lr2;
    int r1 = lane >> 2, c2 = (lane & 3) * 2;
    size_t row1 = (size_t)b * S_LEN + q0 + wid * 16 + r1;
    size_t row2 = row1 + 8;
    #pragma unroll
    for (int nt = 0; nt < 16; nt++) {
        int col = h * HD + nt * 8 + c2;
        *(uint32_t*)(Oh + row1 * DIMM + col) = pack_h(o[nt][0] * i1, o[nt][1] * i1);
        *(uint32_t*)(Oh + row2 * DIMM + col) = pack_h(o[nt][2] * i2, o[nt][3] * i2);
    }
}

// ---------------------------------------------------------------------------
extern "C" void kernel_launch(void* const* d_in, const int* in_sizes, int n_in,
                              void* d_out, int out_size)
{
    const float* x     = (const float*)d_in[0];   // [2,2048,2048]
    const float* w_qkv = (const float*)d_in[1];   // [2048,6144]
    const float* w_out = (const float*)d_in[2];   // [2048,2048]
    float* out = (float*)d_out;                   // [2,2048,2048]

    __half *xh, *xl, *wqh, *woh, *ah, *qh, *ql, *kh, *vh;
    cudaGetSymbolAddress((void**)&xh, g_xh);
    cudaGetSymbolAddress((void**)&xl, g_xl);
    cudaGetSymbolAddress((void**)&wqh, g_wqT_h);
    cudaGetSymbolAddress((void**)&woh, g_woT_h);
    cudaGetSymbolAddress((void**)&ah, g_ah);
    cudaGetSymbolAddress((void**)&qh, g_qh);
    cudaGetSymbolAddress((void**)&ql, g_ql);
    cudaGetSymbolAddress((void**)&kh, g_kh);
    cudaGetSymbolAddress((void**)&vh, g_vh);

    const int SMEM2 = 4 * 3 * TILE_B;   // 98304  (2-term, 4 stages)
    const int SMEM1 = 6 * 2 * TILE_B;   // 98304  (1-term, 6 stages)
    cudaFuncSetAttribute((const void*)gemm_mma<2, 4, true>,
                         cudaFuncAttributeMaxDynamicSharedMemorySize, SMEM2);
    cudaFuncSetAttribute((const void*)gemm_mma<1, 6, true>,
                         cudaFuncAttributeMaxDynamicSharedMemorySize, SMEM1);
    cudaFuncSetAttribute((const void*)gemm_mma<1, 6, false>,
                         cudaFuncAttributeMaxDynamicSharedMemorySize, SMEM1);
    cudaFuncSetAttribute((const void*)attn_mma,
                         cudaFuncAttributeMaxDynamicSharedMemorySize, ATT_SMEM);

    // split x -> fp16 hi/lo
    {
        int n4 = (MROWS * DIMM) / 4;
        split_kernel<<<(n4 + 255) / 256, 256>>>(x, xh, xl, n4);
    }
    // transpose weights -> fp16 hi only
    {
        dim3 tb(32, 8);
        transpose_half<<<dim3(QKV_W / 32, DIMM / 32), tb>>>(w_qkv, wqh, DIMM, QKV_W);
        transpose_half<<<dim3(DIMM / 32, DIMM / 32), tb>>>(w_out, woh, DIMM, DIMM);
    }
    // 1a) Q projection (2-term, 4 stages)
    gemm_mma<2, 4, true><<<dim3(2048 / 128, MROWS / 128), 256, SMEM2>>>(
        xh, xl, wqh, nullptr, qh, ql, nullptr, nullptr,
        0, MROWS, 2048, DIMM);
    // 1b) K/V projection (1-term, 6 stages — deeper prefetch)
    gemm_mma<1, 6, true><<<dim3(4096 / 128, MROWS / 128), 256, SMEM1>>>(
        xh, nullptr, wqh + (size_t)2048 * DIMM, nullptr,
        nullptr, nullptr, kh, vh,
        2048, MROWS, 4096, DIMM);

    // 2) Attention -> writes fp16 O
    {
        dim3 grid(S_LEN / 128, NHEADS, BATCH);
        attn_mma<<<grid, 256, ATT_SMEM>>>(qh, ql, kh, vh, ah);
    }

    // 3) Output projection -> fp32 out (1-term, 6 stages)
    gemm_mma<1, 6, false><<<dim3(DIMM / 128, MROWS / 128), 256, SMEM1>>>(
        ah, nullptr, woh, out, nullptr, nullptr, nullptr, nullptr,
        0, MROWS, DIMM, DIMM);
}

// round 15
// speedup vs baseline: 1.2436x; 1.2007x over previous
#include <cuda_runtime.h>
#include <cuda_fp16.h>
#include <math_constants.h>
#include <cstdint>
#include <cstddef>

#define S_LEN  2048
#define DIMM   2048
#define NHEADS 16
#define HD     128
#define QKV_W  6144
#define BATCH  2
#define MROWS  (BATCH * S_LEN)   // 4096
#define SCALE_F 0.08838834764831845f

// ---------------------------------------------------------------------------
// Scratch (__device__ globals: allocation-free rule)
// ---------------------------------------------------------------------------
__device__ __half  g_xh[(size_t)MROWS * DIMM];
__device__ __half  g_wqT_h[(size_t)QKV_W * DIMM];   // [6144,2048] K-major (B^T), hi only
__device__ __half  g_woT_h[(size_t)DIMM * DIMM];    // [2048,2048] K-major, hi only
__device__ __half  g_ah[(size_t)MROWS * DIMM];      // attention out (fp16)
// per-(b,h) attention operands [b][h][s][128], all fp16 hi-only
#define HSD ((size_t)BATCH * NHEADS * S_LEN * HD)
__device__ __half  g_qh[HSD];
__device__ __half  g_kh[HSD];
__device__ __half  g_vh[HSD];

// ---------------------------------------------------------------------------
// helpers
// ---------------------------------------------------------------------------
__device__ __forceinline__ uint32_t smem_u32(const void* p) {
    uint32_t a;
    asm("{ .reg .u64 t; cvta.to.shared.u64 t, %1; cvt.u32.u64 %0, t; }"
        : "=r"(a) : "l"(p));
    return a;
}
__device__ __forceinline__ void cp16(uint32_t dst, const void* src) {
    asm volatile("cp.async.cg.shared.global [%0], [%1], 16;"
                 :: "r"(dst), "l"(src) : "memory");
}
__device__ __forceinline__ void cp_commit() {
    asm volatile("cp.async.commit_group;" ::: "memory");
}
__device__ __forceinline__ void cp_wait1() {
    asm volatile("cp.async.wait_group 1;" ::: "memory");
}
template <int N>
__device__ __forceinline__ void cp_waitn() {
    asm volatile("cp.async.wait_group %0;" :: "n"(N) : "memory");
}
__device__ __forceinline__ void mma_f16(float* d, const uint32_t* a,
                                        const uint32_t* b) {
    asm volatile(
        "mma.sync.aligned.m16n8k16.row.col.f32.f16.f16.f32 "
        "{%0,%1,%2,%3}, {%4,%5,%6,%7}, {%8,%9}, {%0,%1,%2,%3};"
        : "+f"(d[0]), "+f"(d[1]), "+f"(d[2]), "+f"(d[3])
        : "r"(a[0]), "r"(a[1]), "r"(a[2]), "r"(a[3]), "r"(b[0]), "r"(b[1]));
}
__device__ __forceinline__ void ldsm4(uint32_t* r, uint32_t addr) {
    asm volatile("ldmatrix.sync.aligned.m8n8.x4.shared.b16 {%0,%1,%2,%3}, [%4];"
                 : "=r"(r[0]), "=r"(r[1]), "=r"(r[2]), "=r"(r[3]) : "r"(addr));
}
__device__ __forceinline__ void ldsm4t(uint32_t* r, uint32_t addr) {
    asm volatile("ldmatrix.sync.aligned.m8n8.x4.trans.shared.b16 {%0,%1,%2,%3}, [%4];"
                 : "=r"(r[0]), "=r"(r[1]), "=r"(r[2]), "=r"(r[3]) : "r"(addr));
}
__device__ __forceinline__ uint32_t pack_h(float x, float y) {
    return ((uint32_t)__half_as_ushort(__float2half_rn(y)) << 16)
         | (uint32_t)__half_as_ushort(__float2half_rn(x));
}

// ---------------------------------------------------------------------------
// Conversion kernels
// ---------------------------------------------------------------------------
__global__ void convert_half(const float* __restrict__ in,
                             __half* __restrict__ hi, int n4)
{
    int i = blockIdx.x * blockDim.x + threadIdx.x;
    if (i >= n4) return;
    float4 v = ((const float4*)in)[i];
    ((uint32_t*)hi)[i * 2]     = pack_h(v.x, v.y);
    ((uint32_t*)hi)[i * 2 + 1] = pack_h(v.z, v.w);
}

// in [R,C] fp32 -> out [C,R] fp16 (hi only)
__global__ void transpose_half(const float* __restrict__ in,
                               __half* __restrict__ oh, int R, int C)
{
    __shared__ float t[32][33];
    int bx = blockIdx.x * 32, by = blockIdx.y * 32;
    int x = threadIdx.x, y = threadIdx.y;           // 32 x 8
    #pragma unroll
    for (int i = 0; i < 32; i += 8)
        t[y + i][x] = in[(size_t)(by + y + i) * C + bx + x];
    __syncthreads();
    #pragma unroll
    for (int i = 0; i < 32; i += 8) {
        float v = t[x][y + i];
        oh[(size_t)(bx + y + i) * R + by + x] = __float2half_rn(v);
    }
}

// ---------------------------------------------------------------------------
// 1-term mma.sync fp16 GEMM: C = Ah @ Bh^T.
// 128x128 CTA tile, BK=32, 256 thr, 8 warps 4x2 (warp tile 32x64).
// 6-stage cp.async pipeline, single sync/chunk, 2 CTAs/SM.
// SPLIT_OUT epilogue routes cols to Q(hi,scaled) / K(hi) / V(hi).
// ---------------------------------------------------------------------------
#define ROWB 64
#define TILE_B (128 * ROWB)        // 8192
#define G_STAGES 6
#define G_SMEM (G_STAGES * 2 * TILE_B)   // 98304

__device__ __forceinline__ uint32_t swoff(int row, int c16) {
    return (uint32_t)(row * ROWB + (((c16 + (row >> 1)) & 3) << 4));
}

template <bool SPLIT_OUT>
__global__ __launch_bounds__(256, 2) void gemm_mma(
    const __half* __restrict__ Ah, const __half* __restrict__ Bh,
    float* __restrict__ C,
    __half* __restrict__ QH, __half* __restrict__ KH, __half* __restrict__ VH,
    int M, int N, int K)
{
    extern __shared__ char smem[];
    const uint32_t smem_base = smem_u32(smem);
    const int tid  = threadIdx.x;
    const int wid  = tid >> 5;
    const int lane = tid & 31;
    const int wm   = wid & 3;          // 0..3  (m dir, 32 rows)
    const int wn   = wid >> 2;         // 0..1  (n dir, 64 cols)
    const int bm = blockIdx.y * 128;
    const int bn = blockIdx.x * 128;

    const int lr = tid >> 1;            // load row 0..127
    const int lcb = (tid & 1) * 2;      // chunk base 0 or 2
    const int r0 = lane >> 2;
    const int c0 = (lane & 3) * 2;

    const int a_row_l = lane & 15;
    const int a_cx    = lane >> 4;
    const int b_row_l = (lane & 7) + ((lane >> 4) << 3);
    const int b_cx    = (lane >> 3) & 1;

    float acc[2][8][4];
    #pragma unroll
    for (int mt = 0; mt < 2; mt++)
        #pragma unroll
        for (int nt = 0; nt < 8; nt++)
            #pragma unroll
            for (int j = 0; j < 4; j++) acc[mt][nt][j] = 0.0f;

    const int NC = K / 32;

    auto issue_tile = [&](const __half* src, int row0, int k0,
                          uint32_t dstbase) {
        const char* g = (const char*)(src + (size_t)(row0 + lr) * K + k0);
        cp16(dstbase + swoff(lr, lcb),     g + lcb * 16);
        cp16(dstbase + swoff(lr, lcb + 1), g + lcb * 16 + 16);
    };
    auto issue_stage = [&](int c) {
        uint32_t base = smem_base + (c % G_STAGES) * (2 * TILE_B);
        int k0 = c * 32;
        issue_tile(Ah, bm, k0, base);
        issue_tile(Bh, bn, k0, base + TILE_B);
    };

    #pragma unroll
    for (int s = 0; s < G_STAGES - 1; s++) {
        issue_stage(s);
        cp_commit();
    }

    for (int c = 0; c < NC; c++) {
        cp_waitn<G_STAGES - 2>();
        __syncthreads();
        if (c + G_STAGES - 1 < NC) issue_stage(c + G_STAGES - 1);
        cp_commit();

        const uint32_t sb  = smem_base + (c % G_STAGES) * (2 * TILE_B);
        const uint32_t sAh = sb;
        const uint32_t sBh = sb + TILE_B;

        #pragma unroll
        for (int kss = 0; kss < 2; kss++) {
            const int ks = kss ^ (wid & 1);    // warp-staggered phases
            uint32_t ah[2][4], bx[8][2];

            #pragma unroll
            for (int np = 0; np < 4; np++) {
                int row = wn * 64 + np * 16 + b_row_l;
                uint32_t th[4];
                ldsm4(th, sBh + swoff(row, ks * 2 + b_cx));
                bx[np * 2][0] = th[0]; bx[np * 2][1] = th[1];
                bx[np * 2 + 1][0] = th[2]; bx[np * 2 + 1][1] = th[3];
            }
            #pragma unroll
            for (int mt = 0; mt < 2; mt++) {
                int row = wm * 32 + mt * 16 + a_row_l;
                ldsm4(ah[mt], sAh + swoff(row, ks * 2 + a_cx));
            }
            #pragma unroll
            for (int mt = 0; mt < 2; mt++)
                #pragma unroll
                for (int nt = 0; nt < 8; nt++)
                    mma_f16(acc[mt][nt], ah[mt], bx[nt]);
        }
    }

    // epilogue
    if (!SPLIT_OUT) {
        #pragma unroll
        for (int mt = 0; mt < 2; mt++) {
            int row = bm + wm * 32 + mt * 16 + r0;
            #pragma unroll
            for (int nt = 0; nt < 8; nt++) {
                int col = bn + wn * 64 + nt * 8 + c0;
                float* p0 = C + (size_t)row * N + col;
                float* p1 = p0 + 8 * (size_t)N;
                *(float2*)p0 = make_float2(acc[mt][nt][0], acc[mt][nt][1]);
                *(float2*)p1 = make_float2(acc[mt][nt][2], acc[mt][nt][3]);
            }
        }
    } else {
        const int sec = bn >> 11;           // 0=Q, 1=K, 2=V
        const int hh  = (bn >> 7) & 15;
        const float sc = (sec == 0) ? SCALE_F : 1.0f;
        __half* OUT = (sec == 0) ? QH : ((sec == 1) ? KH : VH);
        #pragma unroll
        for (int mt = 0; mt < 2; mt++) {
            int row = bm + wm * 32 + mt * 16 + r0;
            #pragma unroll
            for (int nt = 0; nt < 8; nt++) {
                int d = (wn * 64 + nt * 8 + c0) & 127;
                #pragma unroll
                for (int half = 0; half < 2; half++) {
                    int rr = row + half * 8;
                    int bb = rr >> 11, ss = rr & 2047;
                    size_t dst = (((size_t)(bb * NHEADS + hh)) * S_LEN + ss) * HD + d;
                    *(uint32_t*)(OUT + dst) =
                        pack_h(acc[mt][nt][half * 2] * sc,
                               acc[mt][nt][half * 2 + 1] * sc);
                }
            }
        }
    }
}

// ---------------------------------------------------------------------------
// Tensor-core flash attention, fp16 1-term (Q/K/V all hi-only).
// 1 CTA per (b,h,128 queries), 8 warps x 16 query rows, BKV=64, 2-stage K/V.
// smem: Q 32KB + 2 x 32KB = 96KB -> 2 CTAs/SM. 32 iterations (halved overhead).
// ---------------------------------------------------------------------------
#define BKV 64
#define KV_STAGE_B 32768           // Kh 16KB + Vh 16KB
#define ATT_SMEM (32768 + 2 * KV_STAGE_B)   // 98304

__global__ __launch_bounds__(256, 2) void attn_mma(
    const __half* __restrict__ Qh, const __half* __restrict__ Kh,
    const __half* __restrict__ Vh, __half* __restrict__ Oh)
{
    extern __shared__ char smem[];
    const uint32_t sb0 = smem_u32(smem);
    const uint32_t sQ = sb0;
    const int tid = threadIdx.x, wid = tid >> 5, lane = tid & 31;
    const int q0 = blockIdx.x * 128, h = blockIdx.y, b = blockIdx.z;

    const size_t hb = ((size_t)(b * NHEADS + h)) * S_LEN * HD;
    const __half* gqh = Qh + hb + (size_t)q0 * HD;
    const __half* gkh = Kh + hb;
    const __half* gvh = Vh + hb;

    // Q (128 rows x 256B), hi only
    {
        int r = tid >> 1, cb = (tid & 1) * 8;
        const char* g0 = (const char*)(gqh + (size_t)r * HD);
        uint32_t d0 = sQ + r * 256;
        #pragma unroll
        for (int j = 0; j < 8; j++) {
            int c = cb + j;
            uint32_t sw = (uint32_t)((c ^ (r & 7)) << 4);
            cp16(d0 + sw, g0 + c * 16);
        }
    }
    auto ld_stage = [&](int t) {
        uint32_t base = sb0 + 32768 + (t & 1) * KV_STAGE_B;
        int s0 = t * BKV;
        int r = tid >> 2;          // 0..63
        int cb = (tid & 3) * 4;    // 0,4,8,12
        const char* gk = (const char*)(gkh + (size_t)(s0 + r) * HD);
        const char* gv = (const char*)(gvh + (size_t)(s0 + r) * HD);
        uint32_t dr = base + r * 256;
        #pragma unroll
        for (int j = 0; j < 4; j++) {
            int c = cb + j;
            uint32_t sw = (uint32_t)((c ^ (r & 7)) << 4);
            cp16(dr + sw,         gk + c * 16);
            cp16(dr + 16384 + sw, gv + c * 16);
        }
    };

    ld_stage(0); cp_commit();      // Q rides in group 0
    ld_stage(1); cp_commit();

    const int aq_row = wid * 16 + (lane & 15);
    const uint32_t aq_base = (uint32_t)(aq_row * 256);
    const int aq_r7 = aq_row & 7;
    const int aq_cx = lane >> 4;
    const int bk_row = (lane & 7) + ((lane >> 4) << 3);
    const int bk_cx = (lane >> 3) & 1;
    const int bv_row = (lane & 7) + (((lane >> 3) & 1) << 3);
    const int bv_cx = lane >> 4;

    float o[16][4];
    #pragma unroll
    for (int nt = 0; nt < 16; nt++) { o[nt][0]=o[nt][1]=o[nt][2]=o[nt][3]=0.f; }
    float mr1 = -CUDART_INF_F, mr2 = -CUDART_INF_F, lr1 = 0.f, lr2 = 0.f;

    const int NT = S_LEN / BKV;    // 32
    for (int t = 0; t < NT; t++) {
        cp_wait1();
        __syncthreads();

        uint32_t sK = sb0 + 32768 + (t & 1) * KV_STAGE_B;
        uint32_t sV = sK + 16384;

        // ---- S = Q.K^T (1 term), 64 keys ----
        float s[8][4];
        #pragma unroll
        for (int i = 0; i < 8; i++) { s[i][0]=s[i][1]=s[i][2]=s[i][3]=0.f; }

        #pragma unroll
        for (int kt = 0; kt < 8; kt++) {
            uint32_t ah4[4];
            {
                int c16 = kt * 2 + aq_cx;
                ldsm4(ah4, sQ + aq_base + (uint32_t)(((c16 ^ aq_r7)) << 4));
            }
            #pragma unroll
            for (int np = 0; np < 4; np++) {
                int row = np * 16 + bk_row;
                int c16 = kt * 2 + bk_cx;
                uint32_t off = (uint32_t)(row * 256) + (uint32_t)(((c16 ^ (row & 7))) << 4);
                uint32_t bh4[4];
                ldsm4(bh4, sK + off);
                mma_f16(s[2*np],   ah4, bh4);
                mma_f16(s[2*np+1], ah4, bh4 + 2);
            }
        }

        // ---- online softmax (rows r1 = lane>>2 and r1+8), 64 cols ----
        float m1 = s[0][0], m2 = s[0][2];
        #pragma unroll
        for (int i = 0; i < 8; i++) {
            m1 = fmaxf(m1, fmaxf(s[i][0], s[i][1]));
            m2 = fmaxf(m2, fmaxf(s[i][2], s[i][3]));
        }
        m1 = fmaxf(m1, __shfl_xor_sync(0xffffffffu, m1, 1));
        m1 = fmaxf(m1, __shfl_xor_sync(0xffffffffu, m1, 2));
        m2 = fmaxf(m2, __shfl_xor_sync(0xffffffffu, m2, 1));
        m2 = fmaxf(m2, __shfl_xor_sync(0xffffffffu, m2, 2));
        float mn1 = fmaxf(mr1, m1), mn2 = fmaxf(mr2, m2);
        float a1 = __expf(mr1 - mn1), a2 = __expf(mr2 - mn2);
        mr1 = mn1; mr2 = mn2;
        float l1 = 0.f, l2 = 0.f;
        #pragma unroll
        for (int i = 0; i < 8; i++) {
            s[i][0] = __expf(s[i][0] - mn1); s[i][1] = __expf(s[i][1] - mn1);
            s[i][2] = __expf(s[i][2] - mn2); s[i][3] = __expf(s[i][3] - mn2);
            l1 += s[i][0] + s[i][1];
            l2 += s[i][2] + s[i][3];
        }
        l1 += __shfl_xor_sync(0xffffffffu, l1, 1);
        l1 += __shfl_xor_sync(0xffffffffu, l1, 2);
        l2 += __shfl_xor_sync(0xffffffffu, l2, 1);
        l2 += __shfl_xor_sync(0xffffffffu, l2, 2);
        lr1 = lr1 * a1 + l1;
        lr2 = lr2 * a2 + l2;
        #pragma unroll
        for (int nt = 0; nt < 16; nt++) {
            o[nt][0] *= a1; o[nt][1] *= a1; o[nt][2] *= a2; o[nt][3] *= a2;
        }

        // ---- pack P -> fp16 A-fragments (hi only) ----
        uint32_t ph[4][4];
        #pragma unroll
        for (int k2 = 0; k2 < 4; k2++) {
            ph[k2][0] = pack_h(s[2*k2][0],   s[2*k2][1]);
            ph[k2][1] = pack_h(s[2*k2][2],   s[2*k2][3]);
            ph[k2][2] = pack_h(s[2*k2+1][0], s[2*k2+1][1]);
            ph[k2][3] = pack_h(s[2*k2+1][2], s[2*k2+1][3]);
        }

        // ---- O += P.V (1 term), V via ldmatrix.trans ----
        #pragma unroll
        for (int k2 = 0; k2 < 4; k2++) {
            #pragma unroll
            for (int np = 0; np < 8; np++) {
                int row = k2 * 16 + bv_row;
                int c16 = np * 2 + bv_cx;
                uint32_t off = (uint32_t)(row * 256) + (uint32_t)(((c16 ^ (row & 7))) << 4);
                uint32_t v4[4];
                ldsm4t(v4, sV + off);
                mma_f16(o[2*np],   ph[k2], v4);
                mma_f16(o[2*np+1], ph[k2], v4 + 2);
            }
        }

        __syncthreads();          // all warps done reading stage t
        if (t + 2 < NT) ld_stage(t + 2);
        cp_commit();
    }

    // epilogue: normalize, write fp16
    float i1 = 1.f / lr1, i2 = 1.f / lr2;
    int r1 = lane >> 2, c2 = (lane & 3) * 2;
    size_t row1 = (size_t)b * S_LEN + q0 + wid * 16 + r1;
    size_t row2 = row1 + 8;
    #pragma unroll
    for (int nt = 0; nt < 16; nt++) {
        int col = h * HD + nt * 8 + c2;
        *(uint32_t*)(Oh + row1 * DIMM + col) = pack_h(o[nt][0] * i1, o[nt][1] * i1);
        *(uint32_t*)(Oh + row2 * DIMM + col) = pack_h(o[nt][2] * i2, o[nt][3] * i2);
    }
}

// ---------------------------------------------------------------------------
extern "C" void kernel_launch(void* const* d_in, const int* in_sizes, int n_in,
                              void* d_out, int out_size)
{
    const float* x     = (const float*)d_in[0];   // [2,2048,2048]
    const float* w_qkv = (const float*)d_in[1];   // [2048,6144]
    const float* w_out = (const float*)d_in[2];   // [2048,2048]
    float* out = (float*)d_out;                   // [2,2048,2048]

    __half *xh, *wqh, *woh, *ah, *qh, *kh, *vh;
    cudaGetSymbolAddress((void**)&xh, g_xh);
    cudaGetSymbolAddress((void**)&wqh, g_wqT_h);
    cudaGetSymbolAddress((void**)&woh, g_woT_h);
    cudaGetSymbolAddress((void**)&ah, g_ah);
    cudaGetSymbolAddress((void**)&qh, g_qh);
    cudaGetSymbolAddress((void**)&kh, g_kh);
    cudaGetSymbolAddress((void**)&vh, g_vh);

    cudaFuncSetAttribute((const void*)gemm_mma<true>,
                         cudaFuncAttributeMaxDynamicSharedMemorySize, G_SMEM);
    cudaFuncSetAttribute((const void*)gemm_mma<false>,
                         cudaFuncAttributeMaxDynamicSharedMemorySize, G_SMEM);
    cudaFuncSetAttribute((const void*)attn_mma,
                         cudaFuncAttributeMaxDynamicSharedMemorySize, ATT_SMEM);

    // convert x -> fp16 (hi only)
    {
        int n4 = (MROWS * DIMM) / 4;
        convert_half<<<(n4 + 255) / 256, 256>>>(x, xh, n4);
    }
    // transpose weights -> fp16 hi only
    {
        dim3 tb(32, 8);
        transpose_half<<<dim3(QKV_W / 32, DIMM / 32), tb>>>(w_qkv, wqh, DIMM, QKV_W);
        transpose_half<<<dim3(DIMM / 32, DIMM / 32), tb>>>(w_out, woh, DIMM, DIMM);
    }
    // 1) QKV projection: single 1-term GEMM over all 6144 columns
    gemm_mma<true><<<dim3(QKV_W / 128, MROWS / 128), 256, G_SMEM>>>(
        xh, wqh, nullptr, qh, kh, vh, MROWS, QKV_W, DIMM);

    // 2) Attention (BKV=64, all 1-term) -> writes fp16 O
    {
        dim3 grid(S_LEN / 128, NHEADS, BATCH);
        attn_mma<<<grid, 256, ATT_SMEM>>>(qh, kh, vh, ah);
    }

    // 3) Output projection -> fp32 out (1-term)
    gemm_mma<false><<<dim3(DIMM / 128, MROWS / 128), 256, G_SMEM>>>(
        ah, woh, out, nullptr, nullptr, nullptr, MROWS, DIMM, DIMM);
}

// round 16
// speedup vs baseline: 1.2787x; 1.0282x over previous
#include <cuda_runtime.h>
#include <cuda_fp16.h>
#include <math_constants.h>
#include <cstdint>
#include <cstddef>

#define S_LEN  2048
#define DIMM   2048
#define NHEADS 16
#define HD     128
#define QKV_W  6144
#define BATCH  2
#define MROWS  (BATCH * S_LEN)   // 4096
// 1/sqrt(128) * log2(e)  — folded into w_qkv Q-columns; softmax uses exp2
#define QSCALE_F (0.08838834764831845f * 1.4426950408889634f)

// ---------------------------------------------------------------------------
// Scratch (__device__ globals: allocation-free rule)
// ---------------------------------------------------------------------------
__device__ __half  g_xh[(size_t)MROWS * DIMM];
__device__ __half  g_wq_h[(size_t)DIMM * QKV_W];    // [2048,6144] natural [K,N]
__device__ __half  g_wo_h[(size_t)DIMM * DIMM];     // [2048,2048] natural [K,N]
__device__ __half  g_ah[(size_t)MROWS * DIMM];      // attention out (fp16)
// per-(b,h) attention operands [b][h][s][128], fp16
#define HSD ((size_t)BATCH * NHEADS * S_LEN * HD)
__device__ __half  g_qh[HSD];
__device__ __half  g_kh[HSD];
__device__ __half  g_vh[HSD];

// ---------------------------------------------------------------------------
// helpers
// ---------------------------------------------------------------------------
__device__ __forceinline__ uint32_t smem_u32(const void* p) {
    uint32_t a;
    asm("{ .reg .u64 t; cvta.to.shared.u64 t, %1; cvt.u32.u64 %0, t; }"
        : "=r"(a) : "l"(p));
    return a;
}
__device__ __forceinline__ void cp16(uint32_t dst, const void* src) {
    asm volatile("cp.async.cg.shared.global [%0], [%1], 16;"
                 :: "r"(dst), "l"(src) : "memory");
}
__device__ __forceinline__ void cp_commit() {
    asm volatile("cp.async.commit_group;" ::: "memory");
}
__device__ __forceinline__ void cp_wait1() {
    asm volatile("cp.async.wait_group 1;" ::: "memory");
}
template <int N>
__device__ __forceinline__ void cp_waitn() {
    asm volatile("cp.async.wait_group %0;" :: "n"(N) : "memory");
}
__device__ __forceinline__ void mma_f16(float* d, const uint32_t* a,
                                        const uint32_t* b) {
    asm volatile(
        "mma.sync.aligned.m16n8k16.row.col.f32.f16.f16.f32 "
        "{%0,%1,%2,%3}, {%4,%5,%6,%7}, {%8,%9}, {%0,%1,%2,%3};"
        : "+f"(d[0]), "+f"(d[1]), "+f"(d[2]), "+f"(d[3])
        : "r"(a[0]), "r"(a[1]), "r"(a[2]), "r"(a[3]), "r"(b[0]), "r"(b[1]));
}
__device__ __forceinline__ void ldsm4(uint32_t* r, uint32_t addr) {
    asm volatile("ldmatrix.sync.aligned.m8n8.x4.shared.b16 {%0,%1,%2,%3}, [%4];"
                 : "=r"(r[0]), "=r"(r[1]), "=r"(r[2]), "=r"(r[3]) : "r"(addr));
}
__device__ __forceinline__ void ldsm4t(uint32_t* r, uint32_t addr) {
    asm volatile("ldmatrix.sync.aligned.m8n8.x4.trans.shared.b16 {%0,%1,%2,%3}, [%4];"
                 : "=r"(r[0]), "=r"(r[1]), "=r"(r[2]), "=r"(r[3]) : "r"(addr));
}
__device__ __forceinline__ uint32_t pack_h(float x, float y) {
    return ((uint32_t)__half_as_ushort(__float2half_rn(y)) << 16)
         | (uint32_t)__half_as_ushort(__float2half_rn(x));
}
__device__ __forceinline__ float ex2f(float x) {
    float y;
    asm("ex2.approx.f32 %0, %1;" : "=f"(y) : "f"(x));
    return y;
}

// ---------------------------------------------------------------------------
// Conversion kernels (no transposes any more)
// ---------------------------------------------------------------------------
__global__ void convert_half(const float* __restrict__ in,
                             __half* __restrict__ hi, int n4)
{
    int i = blockIdx.x * blockDim.x + threadIdx.x;
    if (i >= n4) return;
    float4 v = ((const float4*)in)[i];
    ((uint32_t*)hi)[i * 2]     = pack_h(v.x, v.y);
    ((uint32_t*)hi)[i * 2 + 1] = pack_h(v.z, v.w);
}

// w_qkv [2048][6144]: Q columns (<2048) pre-scaled by 1/sqrt(d) * log2(e)
__global__ void convert_wqkv(const float* __restrict__ in,
                             __half* __restrict__ hi, int n4)
{
    int i = blockIdx.x * blockDim.x + threadIdx.x;
    if (i >= n4) return;
    float4 v = ((const float4*)in)[i];
    int col = (int)(((size_t)i * 4) % QKV_W);
    float sc = (col < 2048) ? QSCALE_F : 1.0f;
    ((uint32_t*)hi)[i * 2]     = pack_h(v.x * sc, v.y * sc);
    ((uint32_t*)hi)[i * 2 + 1] = pack_h(v.z * sc, v.w * sc);
}

// ---------------------------------------------------------------------------
// 1-term mma.sync fp16 GEMM: C = Ah @ B,  A [M,K] K-major, B [K,N] natural.
// B fragments via ldmatrix.trans (same pattern as attention P.V).
// 128x128 CTA tile, BK=32, 256 thr, 8 warps 4x2 (warp tile 32x64).
// 6-stage cp.async pipeline, single sync/chunk, 2 CTAs/SM.
// SPLIT_OUT epilogue routes cols to Q/K/V per-(b,h) arrays.
// ---------------------------------------------------------------------------
#define ROWB 64
#define A_TILE_B (128 * ROWB)        // 8192 (128 rows x 64 B)
#define B_TILE_B (32 * 256)          // 8192 (32 k-rows x 256 B)
#define G_STAGES 6
#define G_SMEM (G_STAGES * (A_TILE_B + B_TILE_B))   // 98304

__device__ __forceinline__ uint32_t swoff(int row, int c16) {
    return (uint32_t)(row * ROWB + (((c16 + (row >> 1)) & 3) << 4));
}
__device__ __forceinline__ uint32_t sw256(int row, int c16) {
    return (uint32_t)(row * 256 + (((c16 ^ (row & 7))) << 4));
}

template <bool SPLIT_OUT>
__global__ __launch_bounds__(256, 2) void gemm_mma(
    const __half* __restrict__ Ah, const __half* __restrict__ Bn,
    float* __restrict__ C,
    __half* __restrict__ QH, __half* __restrict__ KH, __half* __restrict__ VH,
    int M, int N, int K)
{
    extern __shared__ char smem[];
    const uint32_t smem_base = smem_u32(smem);
    const int tid  = threadIdx.x;
    const int wid  = tid >> 5;
    const int lane = tid & 31;
    const int wm   = wid & 3;          // 0..3  (m dir, 32 rows)
    const int wn   = wid >> 2;         // 0..1  (n dir, 64 cols)
    const int bm = blockIdx.y * 128;
    const int bn = blockIdx.x * 128;

    // A loads: 2 chunks of 16B per thread into 64B rows
    const int lrA  = tid >> 1;          // 0..127
    const int lcbA = (tid & 1) * 2;
    // B loads: 2 chunks of 16B per thread into 256B rows (32 rows)
    const int lrB  = tid >> 3;          // 0..31
    const int lcbB = (tid & 7) * 2;

    const int r0 = lane >> 2;
    const int c0 = (lane & 3) * 2;

    const int a_row_l = lane & 15;
    const int a_cx    = lane >> 4;
    // B fragment lane pattern (ldmatrix.trans), mirrors attention V path
    const int b_row_l = (lane & 7) + (((lane >> 3) & 1) << 3);  // k within 16
    const int b_cx    = lane >> 4;                              // n chunk bit

    float acc[2][8][4];
    #pragma unroll
    for (int mt = 0; mt < 2; mt++)
        #pragma unroll
        for (int nt = 0; nt < 8; nt++)
            #pragma unroll
            for (int j = 0; j < 4; j++) acc[mt][nt][j] = 0.0f;

    const int NC = K / 32;

    auto issue_stage = [&](int c) {
        uint32_t base = smem_base + (c % G_STAGES) * (A_TILE_B + B_TILE_B);
        int k0 = c * 32;
        // A tile [128 m][32 k]
        {
            const char* g = (const char*)(Ah + (size_t)(bm + lrA) * K + k0);
            cp16(base + swoff(lrA, lcbA),     g + lcbA * 16);
            cp16(base + swoff(lrA, lcbA + 1), g + lcbA * 16 + 16);
        }
        // B tile [32 k][128 n] natural
        {
            uint32_t bb = base + A_TILE_B;
            const char* g = (const char*)(Bn + (size_t)(k0 + lrB) * N + bn);
            cp16(bb + sw256(lrB, lcbB),     g + lcbB * 16);
            cp16(bb + sw256(lrB, lcbB + 1), g + lcbB * 16 + 16);
        }
    };

    #pragma unroll
    for (int s = 0; s < G_STAGES - 1; s++) {
        issue_stage(s);
        cp_commit();
    }

    for (int c = 0; c < NC; c++) {
        cp_waitn<G_STAGES - 2>();
        __syncthreads();

        const uint32_t sb = smem_base + (c % G_STAGES) * (A_TILE_B + B_TILE_B);
        const uint32_t sA = sb;
        const uint32_t sB = sb + A_TILE_B;

        #pragma unroll
        for (int kss = 0; kss < 2; kss++) {
            const int ks = kss ^ (wid & 1);    // warp-staggered phases
            uint32_t ah[2][4], bx[8][2];

            // B fragments via ldmatrix.trans: rows = k, cols = n
            #pragma unroll
            for (int np = 0; np < 4; np++) {
                int row = ks * 16 + b_row_l;
                int c16 = wn * 8 + np * 2 + b_cx;
                uint32_t th[4];
                ldsm4t(th, sB + sw256(row, c16));
                bx[np * 2][0] = th[0]; bx[np * 2][1] = th[1];
                bx[np * 2 + 1][0] = th[2]; bx[np * 2 + 1][1] = th[3];
            }
            #pragma unroll
            for (int mt = 0; mt < 2; mt++) {
                int row = wm * 32 + mt * 16 + a_row_l;
                ldsm4(ah[mt], sA + swoff(row, ks * 2 + a_cx));
            }
            #pragma unroll
            for (int mt = 0; mt < 2; mt++)
                #pragma unroll
                for (int nt = 0; nt < 8; nt++)
                    mma_f16(acc[mt][nt], ah[mt], bx[nt]);

            if (kss == 0) {   // spread cp.async issue between MMA batches
                if (c + G_STAGES - 1 < NC) issue_stage(c + G_STAGES - 1);
                cp_commit();
            }
        }
    }

    // epilogue
    if (!SPLIT_OUT) {
        #pragma unroll
        for (int mt = 0; mt < 2; mt++) {
            int row = bm + wm * 32 + mt * 16 + r0;
            #pragma unroll
            for (int nt = 0; nt < 8; nt++) {
                int col = bn + wn * 64 + nt * 8 + c0;
                float* p0 = C + (size_t)row * N + col;
                float* p1 = p0 + 8 * (size_t)N;
                *(float2*)p0 = make_float2(acc[mt][nt][0], acc[mt][nt][1]);
                *(float2*)p1 = make_float2(acc[mt][nt][2], acc[mt][nt][3]);
            }
        }
    } else {
        const int sec = bn >> 11;           // 0=Q, 1=K, 2=V
        const int hh  = (bn >> 7) & 15;
        __half* OUT = (sec == 0) ? QH : ((sec == 1) ? KH : VH);
        #pragma unroll
        for (int mt = 0; mt < 2; mt++) {
            int row = bm + wm * 32 + mt * 16 + r0;
            #pragma unroll
            for (int nt = 0; nt < 8; nt++) {
                int d = (wn * 64 + nt * 8 + c0) & 127;
                #pragma unroll
                for (int half = 0; half < 2; half++) {
                    int rr = row + half * 8;
                    int bb = rr >> 11, ss = rr & 2047;
                    size_t dst = (((size_t)(bb * NHEADS + hh)) * S_LEN + ss) * HD + d;
                    *(uint32_t*)(OUT + dst) =
                        pack_h(acc[mt][nt][half * 2], acc[mt][nt][half * 2 + 1]);
                }
            }
        }
    }
}

// ---------------------------------------------------------------------------
// Tensor-core flash attention, fp16 1-term, exp2-based softmax (log2e folded
// into Q via the weight conversion). 1 CTA per (b,h,128 queries), 8 warps,
// BKV=64, 2-stage K/V, 96KB smem -> 2 CTAs/SM.
// ---------------------------------------------------------------------------
#define BKV 64
#define KV_STAGE_B 32768           // Kh 16KB + Vh 16KB
#define ATT_SMEM (32768 + 2 * KV_STAGE_B)   // 98304

__global__ __launch_bounds__(256, 2) void attn_mma(
    const __half* __restrict__ Qh, const __half* __restrict__ Kh,
    const __half* __restrict__ Vh, __half* __restrict__ Oh)
{
    extern __shared__ char smem[];
    const uint32_t sb0 = smem_u32(smem);
    const uint32_t sQ = sb0;
    const int tid = threadIdx.x, wid = tid >> 5, lane = tid & 31;
    const int q0 = blockIdx.x * 128, h = blockIdx.y, b = blockIdx.z;

    const size_t hb = ((size_t)(b * NHEADS + h)) * S_LEN * HD;
    const __half* gqh = Qh + hb + (size_t)q0 * HD;
    const __half* gkh = Kh + hb;
    const __half* gvh = Vh + hb;

    // Q (128 rows x 256B)
    {
        int r = tid >> 1, cb = (tid & 1) * 8;
        const char* g0 = (const char*)(gqh + (size_t)r * HD);
        uint32_t d0 = sQ + r * 256;
        #pragma unroll
        for (int j = 0; j < 8; j++) {
            int c = cb + j;
            cp16(d0 + (uint32_t)((c ^ (r & 7)) << 4), g0 + c * 16);
        }
    }
    auto ld_stage = [&](int t) {
        uint32_t base = sb0 + 32768 + (t & 1) * KV_STAGE_B;
        int s0 = t * BKV;
        int r = tid >> 2;          // 0..63
        int cb = (tid & 3) * 4;    // 0,4,8,12
        const char* gk = (const char*)(gkh + (size_t)(s0 + r) * HD);
        const char* gv = (const char*)(gvh + (size_t)(s0 + r) * HD);
        uint32_t dr = base + r * 256;
        #pragma unroll
        for (int j = 0; j < 4; j++) {
            int c = cb + j;
            uint32_t sw = (uint32_t)((c ^ (r & 7)) << 4);
            cp16(dr + sw,         gk + c * 16);
            cp16(dr + 16384 + sw, gv + c * 16);
        }
    };

    ld_stage(0); cp_commit();      // Q rides in group 0
    ld_stage(1); cp_commit();

    const int aq_row = wid * 16 + (lane & 15);
    const uint32_t aq_base = (uint32_t)(aq_row * 256);
    const int aq_r7 = aq_row & 7;
    const int aq_cx = lane >> 4;
    const int bk_row = (lane & 7) + ((lane >> 4) << 3);
    const int bk_cx = (lane >> 3) & 1;
    const int bv_row = (lane & 7) + (((lane >> 3) & 1) << 3);
    const int bv_cx = lane >> 4;

    float o[16][4];
    #pragma unroll
    for (int nt = 0; nt < 16; nt++) { o[nt][0]=o[nt][1]=o[nt][2]=o[nt][3]=0.f; }
    float mr1 = -CUDART_INF_F, mr2 = -CUDART_INF_F, lr1 = 0.f, lr2 = 0.f;

    const int NT = S_LEN / BKV;    // 32
    for (int t = 0; t < NT; t++) {
        cp_wait1();
        __syncthreads();

        uint32_t sK = sb0 + 32768 + (t & 1) * KV_STAGE_B;
        uint32_t sV = sK + 16384;

        // ---- S = Q.K^T (1 term), 64 keys ----
        float s[8][4];
        #pragma unroll
        for (int i = 0; i < 8; i++) { s[i][0]=s[i][1]=s[i][2]=s[i][3]=0.f; }

        #pragma unroll
        for (int kt = 0; kt < 8; kt++) {
            uint32_t ah4[4];
            {
                int c16 = kt * 2 + aq_cx;
                ldsm4(ah4, sQ + aq_base + (uint32_t)(((c16 ^ aq_r7)) << 4));
            }
            #pragma unroll
            for (int np = 0; np < 4; np++) {
                int row = np * 16 + bk_row;
                int c16 = kt * 2 + bk_cx;
                uint32_t off = (uint32_t)(row * 256) + (uint32_t)(((c16 ^ (row & 7))) << 4);
                uint32_t bh4[4];
                ldsm4(bh4, sK + off);
                mma_f16(s[2*np],   ah4, bh4);
                mma_f16(s[2*np+1], ah4, bh4 + 2);
            }
        }

        // ---- online softmax in log2 space ----
        float m1 = s[0][0], m2 = s[0][2];
        #pragma unroll
        for (int i = 0; i < 8; i++) {
            m1 = fmaxf(m1, fmaxf(s[i][0], s[i][1]));
            m2 = fmaxf(m2, fmaxf(s[i][2], s[i][3]));
        }
        m1 = fmaxf(m1, __shfl_xor_sync(0xffffffffu, m1, 1));
        m1 = fmaxf(m1, __shfl_xor_sync(0xffffffffu, m1, 2));
        m2 = fmaxf(m2, __shfl_xor_sync(0xffffffffu, m2, 1));
        m2 = fmaxf(m2, __shfl_xor_sync(0xffffffffu, m2, 2));
        float mn1 = fmaxf(mr1, m1), mn2 = fmaxf(mr2, m2);
        float a1 = ex2f(mr1 - mn1), a2 = ex2f(mr2 - mn2);
        mr1 = mn1; mr2 = mn2;
        float l1 = 0.f, l2 = 0.f;
        #pragma unroll
        for (int i = 0; i < 8; i++) {
            s[i][0] = ex2f(s[i][0] - mn1); s[i][1] = ex2f(s[i][1] - mn1);
            s[i][2] = ex2f(s[i][2] - mn2); s[i][3] = ex2f(s[i][3] - mn2);
            l1 += s[i][0] + s[i][1];
            l2 += s[i][2] + s[i][3];
        }
        l1 += __shfl_xor_sync(0xffffffffu, l1, 1);
        l1 += __shfl_xor_sync(0xffffffffu, l1, 2);
        l2 += __shfl_xor_sync(0xffffffffu, l2, 1);
        l2 += __shfl_xor_sync(0xffffffffu, l2, 2);
        lr1 = lr1 * a1 + l1;
        lr2 = lr2 * a2 + l2;
        #pragma unroll
        for (int nt = 0; nt < 16; nt++) {
            o[nt][0] *= a1; o[nt][1] *= a1; o[nt][2] *= a2; o[nt][3] *= a2;
        }

        // ---- pack P -> fp16 A-fragments ----
        uint32_t ph[4][4];
        #pragma unroll
        for (int k2 = 0; k2 < 4; k2++) {
            ph[k2][0] = pack_h(s[2*k2][0],   s[2*k2][1]);
            ph[k2][1] = pack_h(s[2*k2][2],   s[2*k2][3]);
            ph[k2][2] = pack_h(s[2*k2+1][0], s[2*k2+1][1]);
            ph[k2][3] = pack_h(s[2*k2+1][2], s[2*k2+1][3]);
        }

        // ---- O += P.V (1 term), V via ldmatrix.trans ----
        #pragma unroll
        for (int k2 = 0; k2 < 4; k2++) {
            #pragma unroll
            for (int np = 0; np < 8; np++) {
                int row = k2 * 16 + bv_row;
                int c16 = np * 2 + bv_cx;
                uint32_t off = (uint32_t)(row * 256) + (uint32_t)(((c16 ^ (row & 7))) << 4);
                uint32_t v4[4];
                ldsm4t(v4, sV + off);
                mma_f16(o[2*np],   ph[k2], v4);
                mma_f16(o[2*np+1], ph[k2], v4 + 2);
            }
        }

        __syncthreads();          // all warps done reading stage t
        if (t + 2 < NT) ld_stage(t + 2);
        cp_commit();
    }

    // epilogue: normalize, write fp16
    float i1 = 1.f / lr1, i2 = 1.f / lr2;
    int r1 = lane >> 2, c2 = (lane & 3) * 2;
    size_t row1 = (size_t)b * S_LEN + q0 + wid * 16 + r1;
    size_t row2 = row1 + 8;
    #pragma unroll
    for (int nt = 0; nt < 16; nt++) {
        int col = h * HD + nt * 8 + c2;
        *(uint32_t*)(Oh + row1 * DIMM + col) = pack_h(o[nt][0] * i1, o[nt][1] * i1);
        *(uint32_t*)(Oh + row2 * DIMM + col) = pack_h(o[nt][2] * i2, o[nt][3] * i2);
    }
}

// ---------------------------------------------------------------------------
extern "C" void kernel_launch(void* const* d_in, const int* in_sizes, int n_in,
                              void* d_out, int out_size)
{
    const float* x     = (const float*)d_in[0];   // [2,2048,2048]
    const float* w_qkv = (const float*)d_in[1];   // [2048,6144]
    const float* w_out = (const float*)d_in[2];   // [2048,2048]
    float* out = (float*)d_out;                   // [2,2048,2048]

    __half *xh, *wqh, *woh, *ah, *qh, *kh, *vh;
    cudaGetSymbolAddress((void**)&xh, g_xh);
    cudaGetSymbolAddress((void**)&wqh, g_wq_h);
    cudaGetSymbolAddress((void**)&woh, g_wo_h);
    cudaGetSymbolAddress((void**)&ah, g_ah);
    cudaGetSymbolAddress((void**)&qh, g_qh);
    cudaGetSymbolAddress((void**)&kh, g_kh);
    cudaGetSymbolAddress((void**)&vh, g_vh);

    cudaFuncSetAttribute((const void*)gemm_mma<true>,
                         cudaFuncAttributeMaxDynamicSharedMemorySize, G_SMEM);
    cudaFuncSetAttribute((const void*)gemm_mma<false>,
                         cudaFuncAttributeMaxDynamicSharedMemorySize, G_SMEM);
    cudaFuncSetAttribute((const void*)attn_mma,
                         cudaFuncAttributeMaxDynamicSharedMemorySize, ATT_SMEM);

    // conversions (no transposes): x, w_qkv (Q cols pre-scaled), w_out
    {
        int n4 = (MROWS * DIMM) / 4;
        convert_half<<<(n4 + 255) / 256, 256>>>(x, xh, n4);
    }
    {
        int n4 = (DIMM * QKV_W) / 4;
        convert_wqkv<<<(n4 + 255) / 256, 256>>>(w_qkv, wqh, n4);
    }
    {
        int n4 = (DIMM * DIMM) / 4;
        convert_half<<<(n4 + 255) / 256, 256>>>(w_out, woh, n4);
    }

    // 1) QKV projection: single 1-term GEMM over all 6144 columns
    gemm_mma<true><<<dim3(QKV_W / 128, MROWS / 128), 256, G_SMEM>>>(
        xh, wqh, nullptr, qh, kh, vh, MROWS, QKV_W, DIMM);

    // 2) Attention (BKV=64, 1-term, exp2 softmax) -> writes fp16 O
    {
        dim3 grid(S_LEN / 128, NHEADS, BATCH);
        attn_mma<<<grid, 256, ATT_SMEM>>>(qh, kh, vh, ah);
    }

    // 3) Output projection -> fp32 out (1-term)
    gemm_mma<false><<<dim3(DIMM / 128, MROWS / 128), 256, G_SMEM>>>(
        ah, woh, out, nullptr, nullptr, nullptr, MROWS, DIMM, DIMM);
}

// round 17
// speedup vs baseline: 1.3157x; 1.0289x over previous
#include <cuda_runtime.h>
#include <cuda_fp16.h>
#include <math_constants.h>
#include <cstdint>
#include <cstddef>

#define S_LEN  2048
#define DIMM   2048
#define NHEADS 16
#define HD     128
#define QKV_W  6144
#define BATCH  2
#define MROWS  (BATCH * S_LEN)   // 4096
// 1/sqrt(128) * log2(e)  — folded into w_qkv Q-columns; softmax uses exp2
#define QSCALE_F (0.08838834764831845f * 1.4426950408889634f)

// ---------------------------------------------------------------------------
// Scratch (__device__ globals: allocation-free rule)
// ---------------------------------------------------------------------------
__device__ __half  g_xh[(size_t)MROWS * DIMM];
__device__ __half  g_wq_h[(size_t)DIMM * QKV_W];    // [2048,6144] natural [K,N]
__device__ __half  g_wo_h[(size_t)DIMM * DIMM];     // [2048,2048] natural [K,N]
__device__ __half  g_ah[(size_t)MROWS * DIMM];      // attention out (fp16)
// per-(b,h) attention operands [b][h][s][128], fp16
#define HSD ((size_t)BATCH * NHEADS * S_LEN * HD)
__device__ __half  g_qh[HSD];
__device__ __half  g_kh[HSD];
__device__ __half  g_vh[HSD];

// ---------------------------------------------------------------------------
// helpers
// ---------------------------------------------------------------------------
__device__ __forceinline__ uint32_t smem_u32(const void* p) {
    uint32_t a;
    asm("{ .reg .u64 t; cvta.to.shared.u64 t, %1; cvt.u32.u64 %0, t; }"
        : "=r"(a) : "l"(p));
    return a;
}
__device__ __forceinline__ void cp16(uint32_t dst, const void* src) {
    asm volatile("cp.async.cg.shared.global [%0], [%1], 16;"
                 :: "r"(dst), "l"(src) : "memory");
}
__device__ __forceinline__ void cp_commit() {
    asm volatile("cp.async.commit_group;" ::: "memory");
}
__device__ __forceinline__ void cp_wait1() {
    asm volatile("cp.async.wait_group 1;" ::: "memory");
}
template <int N>
__device__ __forceinline__ void cp_waitn() {
    asm volatile("cp.async.wait_group %0;" :: "n"(N) : "memory");
}
__device__ __forceinline__ void mma_f16(float* d, const uint32_t* a,
                                        const uint32_t* b) {
    asm volatile(
        "mma.sync.aligned.m16n8k16.row.col.f32.f16.f16.f32 "
        "{%0,%1,%2,%3}, {%4,%5,%6,%7}, {%8,%9}, {%0,%1,%2,%3};"
        : "+f"(d[0]), "+f"(d[1]), "+f"(d[2]), "+f"(d[3])
        : "r"(a[0]), "r"(a[1]), "r"(a[2]), "r"(a[3]), "r"(b[0]), "r"(b[1]));
}
__device__ __forceinline__ void ldsm4(uint32_t* r, uint32_t addr) {
    asm volatile("ldmatrix.sync.aligned.m8n8.x4.shared.b16 {%0,%1,%2,%3}, [%4];"
                 : "=r"(r[0]), "=r"(r[1]), "=r"(r[2]), "=r"(r[3]) : "r"(addr));
}
__device__ __forceinline__ void ldsm4t(uint32_t* r, uint32_t addr) {
    asm volatile("ldmatrix.sync.aligned.m8n8.x4.trans.shared.b16 {%0,%1,%2,%3}, [%4];"
                 : "=r"(r[0]), "=r"(r[1]), "=r"(r[2]), "=r"(r[3]) : "r"(addr));
}
__device__ __forceinline__ uint32_t pack_h(float x, float y) {
    return ((uint32_t)__half_as_ushort(__float2half_rn(y)) << 16)
         | (uint32_t)__half_as_ushort(__float2half_rn(x));
}
__device__ __forceinline__ float ex2f(float x) {
    float y;
    asm("ex2.approx.f32 %0, %1;" : "=f"(y) : "f"(x));
    return y;
}
// pack two fp32 into fp16x2 (x -> low half)
__device__ __forceinline__ uint32_t cvt_h2(float x, float y) {
    uint32_t d;
    asm("cvt.rn.f16x2.f32 %0, %1, %2;" : "=r"(d) : "f"(y), "f"(x));
    return d;
}
// exp2 on both fp16 halves
__device__ __forceinline__ uint32_t h2ex2(uint32_t x) {
    uint32_t y;
    asm("ex2.approx.f16x2 %0, %1;" : "=r"(y) : "r"(x));
    return y;
}

// ---------------------------------------------------------------------------
// Conversion kernels
// ---------------------------------------------------------------------------
__global__ void convert_half(const float* __restrict__ in,
                             __half* __restrict__ hi, int n4)
{
    int i = blockIdx.x * blockDim.x + threadIdx.x;
    if (i >= n4) return;
    float4 v = ((const float4*)in)[i];
    ((uint32_t*)hi)[i * 2]     = pack_h(v.x, v.y);
    ((uint32_t*)hi)[i * 2 + 1] = pack_h(v.z, v.w);
}

// w_qkv [2048][6144]: Q columns (<2048) pre-scaled by 1/sqrt(d) * log2(e)
__global__ void convert_wqkv(const float* __restrict__ in,
                             __half* __restrict__ hi, int n4)
{
    int i = blockIdx.x * blockDim.x + threadIdx.x;
    if (i >= n4) return;
    float4 v = ((const float4*)in)[i];
    int col = (int)(((size_t)i * 4) % QKV_W);
    float sc = (col < 2048) ? QSCALE_F : 1.0f;
    ((uint32_t*)hi)[i * 2]     = pack_h(v.x * sc, v.y * sc);
    ((uint32_t*)hi)[i * 2 + 1] = pack_h(v.z * sc, v.w * sc);
}

// ---------------------------------------------------------------------------
// 1-term mma.sync fp16 GEMM: C = Ah @ B,  A [M,K] K-major, B [K,N] natural.
// (unchanged from R16)
// ---------------------------------------------------------------------------
#define ROWB 64
#define A_TILE_B (128 * ROWB)        // 8192
#define B_TILE_B (32 * 256)          // 8192
#define G_STAGES 6
#define G_SMEM (G_STAGES * (A_TILE_B + B_TILE_B))   // 98304

__device__ __forceinline__ uint32_t swoff(int row, int c16) {
    return (uint32_t)(row * ROWB + (((c16 + (row >> 1)) & 3) << 4));
}
__device__ __forceinline__ uint32_t sw256(int row, int c16) {
    return (uint32_t)(row * 256 + (((c16 ^ (row & 7))) << 4));
}

template <bool SPLIT_OUT>
__global__ __launch_bounds__(256, 2) void gemm_mma(
    const __half* __restrict__ Ah, const __half* __restrict__ Bn,
    float* __restrict__ C,
    __half* __restrict__ QH, __half* __restrict__ KH, __half* __restrict__ VH,
    int M, int N, int K)
{
    extern __shared__ char smem[];
    const uint32_t smem_base = smem_u32(smem);
    const int tid  = threadIdx.x;
    const int wid  = tid >> 5;
    const int lane = tid & 31;
    const int wm   = wid & 3;
    const int wn   = wid >> 2;
    const int bm = blockIdx.y * 128;
    const int bn = blockIdx.x * 128;

    const int lrA  = tid >> 1;
    const int lcbA = (tid & 1) * 2;
    const int lrB  = tid >> 3;
    const int lcbB = (tid & 7) * 2;

    const int r0 = lane >> 2;
    const int c0 = (lane & 3) * 2;

    const int a_row_l = lane & 15;
    const int a_cx    = lane >> 4;
    const int b_row_l = (lane & 7) + (((lane >> 3) & 1) << 3);
    const int b_cx    = lane >> 4;

    float acc[2][8][4];
    #pragma unroll
    for (int mt = 0; mt < 2; mt++)
        #pragma unroll
        for (int nt = 0; nt < 8; nt++)
            #pragma unroll
            for (int j = 0; j < 4; j++) acc[mt][nt][j] = 0.0f;

    const int NC = K / 32;

    auto issue_stage = [&](int c) {
        uint32_t base = smem_base + (c % G_STAGES) * (A_TILE_B + B_TILE_B);
        int k0 = c * 32;
        {
            const char* g = (const char*)(Ah + (size_t)(bm + lrA) * K + k0);
            cp16(base + swoff(lrA, lcbA),     g + lcbA * 16);
            cp16(base + swoff(lrA, lcbA + 1), g + lcbA * 16 + 16);
        }
        {
            uint32_t bb = base + A_TILE_B;
            const char* g = (const char*)(Bn + (size_t)(k0 + lrB) * N + bn);
            cp16(bb + sw256(lrB, lcbB),     g + lcbB * 16);
            cp16(bb + sw256(lrB, lcbB + 1), g + lcbB * 16 + 16);
        }
    };

    #pragma unroll
    for (int s = 0; s < G_STAGES - 1; s++) {
        issue_stage(s);
        cp_commit();
    }

    for (int c = 0; c < NC; c++) {
        cp_waitn<G_STAGES - 2>();
        __syncthreads();

        const uint32_t sb = smem_base + (c % G_STAGES) * (A_TILE_B + B_TILE_B);
        const uint32_t sA = sb;
        const uint32_t sB = sb + A_TILE_B;

        #pragma unroll
        for (int kss = 0; kss < 2; kss++) {
            const int ks = kss ^ (wid & 1);
            uint32_t ah[2][4], bx[8][2];

            #pragma unroll
            for (int np = 0; np < 4; np++) {
                int row = ks * 16 + b_row_l;
                int c16 = wn * 8 + np * 2 + b_cx;
                uint32_t th[4];
                ldsm4t(th, sB + sw256(row, c16));
                bx[np * 2][0] = th[0]; bx[np * 2][1] = th[1];
                bx[np * 2 + 1][0] = th[2]; bx[np * 2 + 1][1] = th[3];
            }
            #pragma unroll
            for (int mt = 0; mt < 2; mt++) {
                int row = wm * 32 + mt * 16 + a_row_l;
                ldsm4(ah[mt], sA + swoff(row, ks * 2 + a_cx));
            }
            #pragma unroll
            for (int mt = 0; mt < 2; mt++)
                #pragma unroll
                for (int nt = 0; nt < 8; nt++)
                    mma_f16(acc[mt][nt], ah[mt], bx[nt]);

            if (kss == 0) {
                if (c + G_STAGES - 1 < NC) issue_stage(c + G_STAGES - 1);
                cp_commit();
            }
        }
    }

    // epilogue
    if (!SPLIT_OUT) {
        #pragma unroll
        for (int mt = 0; mt < 2; mt++) {
            int row = bm + wm * 32 + mt * 16 + r0;
            #pragma unroll
            for (int nt = 0; nt < 8; nt++) {
                int col = bn + wn * 64 + nt * 8 + c0;
                float* p0 = C + (size_t)row * N + col;
                float* p1 = p0 + 8 * (size_t)N;
                *(float2*)p0 = make_float2(acc[mt][nt][0], acc[mt][nt][1]);
                *(float2*)p1 = make_float2(acc[mt][nt][2], acc[mt][nt][3]);
            }
        }
    } else {
        const int sec = bn >> 11;           // 0=Q, 1=K, 2=V
        const int hh  = (bn >> 7) & 15;
        __half* OUT = (sec == 0) ? QH : ((sec == 1) ? KH : VH);
        #pragma unroll
        for (int mt = 0; mt < 2; mt++) {
            int row = bm + wm * 32 + mt * 16 + r0;
            #pragma unroll
            for (int nt = 0; nt < 8; nt++) {
                int d = (wn * 64 + nt * 8 + c0) & 127;
                #pragma unroll
                for (int half = 0; half < 2; half++) {
                    int rr = row + half * 8;
                    int bb = rr >> 11, ss = rr & 2047;
                    size_t dst = (((size_t)(bb * NHEADS + hh)) * S_LEN + ss) * HD + d;
                    *(uint32_t*)(OUT + dst) =
                        pack_h(acc[mt][nt][half * 2], acc[mt][nt][half * 2 + 1]);
                }
            }
        }
    }
}

// ---------------------------------------------------------------------------
// Tensor-core flash attention, fp16 1-term, half2-exp2 softmax, row sums via
// ones-MMA (no shfl for l). 1 CTA per (b,h,128 queries), BKV=64, 2-stage K/V,
// 96KB smem -> 2 CTAs/SM.
// ---------------------------------------------------------------------------
#define BKV 64
#define KV_STAGE_B 32768           // Kh 16KB + Vh 16KB
#define ATT_SMEM (32768 + 2 * KV_STAGE_B)   // 98304

__global__ __launch_bounds__(256, 2) void attn_mma(
    const __half* __restrict__ Qh, const __half* __restrict__ Kh,
    const __half* __restrict__ Vh, __half* __restrict__ Oh)
{
    extern __shared__ char smem[];
    const uint32_t sb0 = smem_u32(smem);
    const uint32_t sQ = sb0;
    const int tid = threadIdx.x, wid = tid >> 5, lane = tid & 31;
    const int q0 = blockIdx.x * 128, h = blockIdx.y, b = blockIdx.z;

    const size_t hb = ((size_t)(b * NHEADS + h)) * S_LEN * HD;
    const __half* gqh = Qh + hb + (size_t)q0 * HD;
    const __half* gkh = Kh + hb;
    const __half* gvh = Vh + hb;

    // Q (128 rows x 256B)
    {
        int r = tid >> 1, cb = (tid & 1) * 8;
        const char* g0 = (const char*)(gqh + (size_t)r * HD);
        uint32_t d0 = sQ + r * 256;
        #pragma unroll
        for (int j = 0; j < 8; j++) {
            int c = cb + j;
            cp16(d0 + (uint32_t)((c ^ (r & 7)) << 4), g0 + c * 16);
        }
    }
    auto ld_stage = [&](int t) {
        uint32_t base = sb0 + 32768 + (t & 1) * KV_STAGE_B;
        int s0 = t * BKV;
        int r = tid >> 2;
        int cb = (tid & 3) * 4;
        const char* gk = (const char*)(gkh + (size_t)(s0 + r) * HD);
        const char* gv = (const char*)(gvh + (size_t)(s0 + r) * HD);
        uint32_t dr = base + r * 256;
        #pragma unroll
        for (int j = 0; j < 4; j++) {
            int c = cb + j;
            uint32_t sw = (uint32_t)((c ^ (r & 7)) << 4);
            cp16(dr + sw,         gk + c * 16);
            cp16(dr + 16384 + sw, gv + c * 16);
        }
    };

    ld_stage(0); cp_commit();      // Q rides in group 0
    ld_stage(1); cp_commit();

    const int aq_row = wid * 16 + (lane & 15);
    const uint32_t aq_base = (uint32_t)(aq_row * 256);
    const int aq_r7 = aq_row & 7;
    const int aq_cx = lane >> 4;
    const int bk_row = (lane & 7) + ((lane >> 4) << 3);
    const int bk_cx = (lane >> 3) & 1;
    const int bv_row = (lane & 7) + (((lane >> 3) & 1) << 3);
    const int bv_cx = lane >> 4;

    const uint32_t ones2 = 0x3C003C00u;           // fp16 {1,1}
    uint32_t bones[2] = {ones2, ones2};

    float o[16][4];
    #pragma unroll
    for (int nt = 0; nt < 16; nt++) { o[nt][0]=o[nt][1]=o[nt][2]=o[nt][3]=0.f; }
    float mr1 = -CUDART_INF_F, mr2 = -CUDART_INF_F, lr1 = 0.f, lr2 = 0.f;

    const int NT = S_LEN / BKV;    // 32
    for (int t = 0; t < NT; t++) {
        cp_wait1();
        __syncthreads();

        uint32_t sK = sb0 + 32768 + (t & 1) * KV_STAGE_B;
        uint32_t sV = sK + 16384;

        // ---- S = Q.K^T (1 term), 64 keys ----
        float s[8][4];
        #pragma unroll
        for (int i = 0; i < 8; i++) { s[i][0]=s[i][1]=s[i][2]=s[i][3]=0.f; }

        #pragma unroll
        for (int kt = 0; kt < 8; kt++) {
            uint32_t ah4[4];
            {
                int c16 = kt * 2 + aq_cx;
                ldsm4(ah4, sQ + aq_base + (uint32_t)(((c16 ^ aq_r7)) << 4));
            }
            #pragma unroll
            for (int np = 0; np < 4; np++) {
                int row = np * 16 + bk_row;
                int c16 = kt * 2 + bk_cx;
                uint32_t off = (uint32_t)(row * 256) + (uint32_t)(((c16 ^ (row & 7))) << 4);
                uint32_t bh4[4];
                ldsm4(bh4, sK + off);
                mma_f16(s[2*np],   ah4, bh4);
                mma_f16(s[2*np+1], ah4, bh4 + 2);
            }
        }

        // ---- row max (fp32, shfl within quad-pairs) ----
        float m1 = s[0][0], m2 = s[0][2];
        #pragma unroll
        for (int i = 0; i < 8; i++) {
            m1 = fmaxf(m1, fmaxf(s[i][0], s[i][1]));
            m2 = fmaxf(m2, fmaxf(s[i][2], s[i][3]));
        }
        m1 = fmaxf(m1, __shfl_xor_sync(0xffffffffu, m1, 1));
        m1 = fmaxf(m1, __shfl_xor_sync(0xffffffffu, m1, 2));
        m2 = fmaxf(m2, __shfl_xor_sync(0xffffffffu, m2, 1));
        m2 = fmaxf(m2, __shfl_xor_sync(0xffffffffu, m2, 2));
        float mn1 = fmaxf(mr1, m1), mn2 = fmaxf(mr2, m2);
        float a1 = ex2f(mr1 - mn1), a2 = ex2f(mr2 - mn2);
        mr1 = mn1; mr2 = mn2;

        // ---- P = exp2(s - m) directly in fp16x2 (half the MUFU ops) ----
        uint32_t ph[4][4];
        #pragma unroll
        for (int k2 = 0; k2 < 4; k2++) {
            ph[k2][0] = h2ex2(cvt_h2(s[2*k2][0]   - mn1, s[2*k2][1]   - mn1));
            ph[k2][1] = h2ex2(cvt_h2(s[2*k2][2]   - mn2, s[2*k2][3]   - mn2));
            ph[k2][2] = h2ex2(cvt_h2(s[2*k2+1][0] - mn1, s[2*k2+1][1] - mn1));
            ph[k2][3] = h2ex2(cvt_h2(s[2*k2+1][2] - mn2, s[2*k2+1][3] - mn2));
        }

        // ---- row sums via ones-MMA (no shfl, fp32 accumulate) ----
        float lac[4] = {0.f, 0.f, 0.f, 0.f};
        #pragma unroll
        for (int k2 = 0; k2 < 4; k2++)
            mma_f16(lac, ph[k2], bones);
        lr1 = lr1 * a1 + lac[0];
        lr2 = lr2 * a2 + lac[2];

        #pragma unroll
        for (int nt = 0; nt < 16; nt++) {
            o[nt][0] *= a1; o[nt][1] *= a1; o[nt][2] *= a2; o[nt][3] *= a2;
        }

        // ---- O += P.V (1 term), V via ldmatrix.trans ----
        #pragma unroll
        for (int k2 = 0; k2 < 4; k2++) {
            #pragma unroll
            for (int np = 0; np < 8; np++) {
                int row = k2 * 16 + bv_row;
                int c16 = np * 2 + bv_cx;
                uint32_t off = (uint32_t)(row * 256) + (uint32_t)(((c16 ^ (row & 7))) << 4);
                uint32_t v4[4];
                ldsm4t(v4, sV + off);
                mma_f16(o[2*np],   ph[k2], v4);
                mma_f16(o[2*np+1], ph[k2], v4 + 2);
            }
        }

        __syncthreads();          // all warps done reading stage t
        if (t + 2 < NT) ld_stage(t + 2);
        cp_commit();
    }

    // epilogue: normalize, write fp16
    float i1 = 1.f / lr1, i2 = 1.f / lr2;
    int r1 = lane >> 2, c2 = (lane & 3) * 2;
    size_t row1 = (size_t)b * S_LEN + q0 + wid * 16 + r1;
    size_t row2 = row1 + 8;
    #pragma unroll
    for (int nt = 0; nt < 16; nt++) {
        int col = h * HD + nt * 8 + c2;
        *(uint32_t*)(Oh + row1 * DIMM + col) = pack_h(o[nt][0] * i1, o[nt][1] * i1);
        *(uint32_t*)(Oh + row2 * DIMM + col) = pack_h(o[nt][2] * i2, o[nt][3] * i2);
    }
}

// ---------------------------------------------------------------------------
extern "C" void kernel_launch(void* const* d_in, const int* in_sizes, int n_in,
                              void* d_out, int out_size)
{
    const float* x     = (const float*)d_in[0];   // [2,2048,2048]
    const float* w_qkv = (const float*)d_in[1];   // [2048,6144]
    const float* w_out = (const float*)d_in[2];   // [2048,2048]
    float* out = (float*)d_out;                   // [2,2048,2048]

    __half *xh, *wqh, *woh, *ah, *qh, *kh, *vh;
    cudaGetSymbolAddress((void**)&xh, g_xh);
    cudaGetSymbolAddress((void**)&wqh, g_wq_h);
    cudaGetSymbolAddress((void**)&woh, g_wo_h);
    cudaGetSymbolAddress((void**)&ah, g_ah);
    cudaGetSymbolAddress((void**)&qh, g_qh);
    cudaGetSymbolAddress((void**)&kh, g_kh);
    cudaGetSymbolAddress((void**)&vh, g_vh);

    cudaFuncSetAttribute((const void*)gemm_mma<true>,
                         cudaFuncAttributeMaxDynamicSharedMemorySize, G_SMEM);
    cudaFuncSetAttribute((const void*)gemm_mma<false>,
                         cudaFuncAttributeMaxDynamicSharedMemorySize, G_SMEM);
    cudaFuncSetAttribute((const void*)attn_mma,
                         cudaFuncAttributeMaxDynamicSharedMemorySize, ATT_SMEM);

    // conversions: x, w_qkv (Q cols pre-scaled), w_out
    {
        int n4 = (MROWS * DIMM) / 4;
        convert_half<<<(n4 + 255) / 256, 256>>>(x, xh, n4);
    }
    {
        int n4 = (DIMM * QKV_W) / 4;
        convert_wqkv<<<(n4 + 255) / 256, 256>>>(w_qkv, wqh, n4);
    }
    {
        int n4 = (DIMM * DIMM) / 4;
        convert_half<<<(n4 + 255) / 256, 256>>>(w_out, woh, n4);
    }

    // 1) QKV projection: single 1-term GEMM over all 6144 columns
    gemm_mma<true><<<dim3(QKV_W / 128, MROWS / 128), 256, G_SMEM>>>(
        xh, wqh, nullptr, qh, kh, vh, MROWS, QKV_W, DIMM);

    // 2) Attention (BKV=64, 1-term, half2-exp2 softmax) -> writes fp16 O
    {
        dim3 grid(S_LEN / 128, NHEADS, BATCH);
        attn_mma<<<grid, 256, ATT_SMEM>>>(qh, kh, vh, ah);
    }

    // 3) Output projection -> fp32 out (1-term)
    gemm_mma<false><<<dim3(DIMM / 128, MROWS / 128), 256, G_SMEM>>>(
        ah, woh, out, nullptr, nullptr, nullptr, MROWS, DIMM, DIMM);
}